// round 9
// baseline (speedup 1.0000x reference)
#include <cuda_runtime.h>

// Problem dims
#define T_STEPS 32
#define NB      16
#define CIN     2
#define COUT    8
#define HH      128
#define WW      128
#define KK      5
#define PADL    2
#define HP      (HH + 2*PADL)   // 132
#define WP      (WW + 2*PADL)   // 132
#define NW      (COUT*CIN*KK*KK) // 400

// Tiling
#define TH 8
#define TW 32
#define PH (TH + 4)   // 12
#define PW 36         // halo window width (TW+4)
#define PW2 37        // trn padded width
#define NT ((WW/TW) * (HH/TH) * NB)   // 1024 tiles

// Persistent state (device globals: allocation-free)
__device__ float g_v[NB*COUT*HH*WW];          // membrane potential
__device__ float g_tp[NB*COUT*HH*WW];         // post trace
__device__ float g_trpre[2][NB*CIN*HP*WP];    // pre trace (padded grid), double buffered
__device__ float g_w[NW];                     // current weights
__device__ float g_part[NW * NT];             // per-tile dw partials
__device__ int   g_act[NB*2];                 // "any spike ever" per (batch, o-group)
__device__ int   g_anyact;                    // any spike ever, anywhere
__device__ unsigned g_bar_count;              // grid barrier ticket counter

__global__ void k_init(const float* __restrict__ w0) {
    int idx = blockIdx.x * blockDim.x + threadIdx.x;
    int stride = gridDim.x * blockDim.x;
    for (int i = idx; i < NB*COUT*HH*WW; i += stride) { g_v[i] = 0.f; g_tp[i] = 0.f; }
    for (int i = idx; i < NB*CIN*HP*WP; i += stride) { g_trpre[0][i] = 0.f; g_trpre[1][i] = 0.f; }
    if (idx < NW) g_w[idx] = w0[idx];
    if (idx < NB*2) g_act[idx] = 0;
    if (idx == 0) { g_anyact = 0; g_bar_count = 0u; }
}

// Persistent kernel: all T steps, software grid barrier between conv-phase
// and weight-update phase. Grid is sized by the host to guaranteed-resident
// block count, so the spin barrier cannot deadlock.
__global__ __launch_bounds__(256, 4)
void k_persist(const float* __restrict__ x_seq, float* __restrict__ out, int ngrid) {
    __shared__ float trn[CIN][PH][PW2];                 // NEW pre-trace patch
    __shared__ __align__(16) float tp_s[TH][TW][COUT];  // NEW post trace [row][col][o]
    __shared__ unsigned long long xmask[CIN][PH];       // x nonzero bitmask per halo row
    __shared__ unsigned int smask[TH][COUT];            // spike bitmask per (row, o)
    __shared__ __align__(16) float wt[50*COUT];         // weights transposed: [tap][o]
    __shared__ float red[NW][TH];                       // per-row dw partials
    __shared__ float sbuf[256];
    __shared__ int act_prior[2];

    const int tid = threadIdx.x;
    const int bid = blockIdx.x;
    unsigned bar_target = 0;

    for (int t = 0; t < T_STEPS; t++) {
        const int cur = t & 1;

        // Load weights transposed (L1-bypass: g_w updated by another block).
        for (int j = tid; j < NW; j += 256) {
            int o   = j / 50;
            int tap = j - o * 50;
            wt[tap*COUT + o] = __ldcg(&g_w[j]);
        }

        for (int tile = bid; tile < NT; tile += ngrid) {
            const int b   = tile >> 6;           // tile = tx + 4*(ty + 16*b)
            const int ty0 = ((tile >> 2) & 15) * TH;
            const int tx0 = (tile & 3) * TW;

            __syncthreads();   // smem reuse guard (prev tile / wt load done)
            if (tid < CIN*PH) ((unsigned long long*)xmask)[tid] = 0ull;
            if (tid < 2) act_prior[tid] = __ldcg(&g_act[b*2 + tid]);
            __syncthreads();

            const float* xt  = x_seq + (((size_t)t*NB + b) * CIN) * HH * WW;
            const float* tro = g_trpre[cur]     + (size_t)b * CIN * HP * WP;
            float*       trw = g_trpre[cur ^ 1] + (size_t)b * CIN * HP * WP;

            const int ownH = (ty0 + TH == HH) ? PH : TH;
            const int ownW = (tx0 + TW == WW) ? PW : TW;

            // Phase 0: pre-trace update + x bitmask build.
            for (int idx = tid; idx < CIN*PH*PW; idx += 256) {
                int i   = idx / (PH*PW);
                int rem = idx % (PH*PW);
                int r = rem / PW, c = rem % PW;
                int u = ty0 + r, vv = tx0 + c;
                int xr = u - PADL, xc = vv - PADL;
                float xv = 0.f;
                if (xr >= 0 && xr < HH && xc >= 0 && xc < WW)
                    xv = xt[(i*HH + xr)*WW + xc];
                float to = __ldcg(&tro[(i*HP + u)*WP + vv]);  // halo crosses blocks
                float tn = to - to / 30.0f + xv;
                trn[i][r][c] = tn;
                if (r < ownH && c < ownW)
                    trw[(i*HP + u)*WP + vv] = tn;
                if (xv != 0.f)
                    atomicOr(&xmask[i][r], 1ull << c);
            }
            __syncthreads();

            // Phase 1: sparse conv + LIF + traces + spike ballots.
            const int px = tid >> 5;
            const int py = tid & 31;
            int loc0, loc1;
            {
                float y[COUT];
                #pragma unroll
                for (int o = 0; o < COUT; o++) y[o] = 0.f;

                #pragma unroll
                for (int i = 0; i < CIN; i++) {
                    unsigned m = 0;
                    #pragma unroll
                    for (int kh = 0; kh < KK; kh++)
                        m |= (unsigned)((xmask[i][px + kh] >> py) & 0x1Full) << (kh*5);
                    while (m) {
                        int bpos = __ffs(m) - 1;
                        m &= m - 1;
                        const float* wp = &wt[(i*25 + bpos)*COUT];
                        float4 wa = *reinterpret_cast<const float4*>(wp);
                        float4 wb = *reinterpret_cast<const float4*>(wp + 4);
                        y[0] += wa.x; y[1] += wa.y; y[2] += wa.z; y[3] += wa.w;
                        y[4] += wb.x; y[5] += wb.y; y[6] += wb.z; y[7] += wb.w;
                    }
                }

                const int gx = ty0 + px, gy = tx0 + py;
                const size_t base = (size_t)b * COUT * HH * WW + (size_t)gx * WW + gy;
                float* outp = out + ((size_t)t * NB + b) * COUT * HH * WW + (size_t)gx * WW + gy;
                float tpv[COUT];
                unsigned ball[COUT];
                #pragma unroll
                for (int o = 0; o < COUT; o++) {
                    size_t gi = base + (size_t)o * HH * WW;
                    float v = g_v[gi];                     // tile-private (same SM)
                    v = v + (y[o] - v) / 100.0f;           // LIF charge
                    float s = (v >= 1.0f) ? 1.f : 0.f;     // fire
                    v = v * (1.f - s);                     // hard reset
                    g_v[gi] = v;
                    float tq = g_tp[gi];
                    tq = tq - tq / 30.0f + s;              // post trace
                    g_tp[gi] = tq;
                    outp[(size_t)o * HH * WW] = s;
                    tpv[o] = tq;
                    ball[o] = __ballot_sync(0xffffffffu, s != 0.f);
                    if (py == 0) smask[px][o] = ball[o];
                }
                *reinterpret_cast<float4*>(&tp_s[px][py][0]) = make_float4(tpv[0], tpv[1], tpv[2], tpv[3]);
                *reinterpret_cast<float4*>(&tp_s[px][py][4]) = make_float4(tpv[4], tpv[5], tpv[6], tpv[7]);
                loc0 = (ball[0] | ball[1] | ball[2] | ball[3]) != 0;
                loc1 = (ball[4] | ball[5] | ball[6] | ball[7]) != 0;
            }
            const int any0 = __syncthreads_or(loc0);
            const int any1 = __syncthreads_or(loc1);
            if (tid == 0) {
                if (any0 && !act_prior[0]) atomicOr(&g_act[b*2 + 0], 1);
                if (any1 && !act_prior[1]) atomicOr(&g_act[b*2 + 1], 1);
                if (any0 | any1) atomicOr(&g_anyact, 1);
            }

            // Phase 2: sparse dw partials. 160 threads = (px:8) x (og:2, ii:2, kh:5).
            if (tid < 160) {
                const int qx = tid / 20;
                const int g  = tid - qx * 20;
                const int og = g & 1;
                const int ii = (g >> 1) & 1;
                const int kh = g >> 2;

                float a[KK][4];
                #pragma unroll
                for (int kw = 0; kw < KK; kw++)
                    #pragma unroll
                    for (int c = 0; c < 4; c++) a[kw][c] = 0.f;

                // Term A: tp (x) correlation — exact skip while tp == 0.
                const int act = og ? (act_prior[1] | any1) : (act_prior[0] | any0);
                if (act) {
                    unsigned long long m = xmask[ii][qx + kh];
                    const float* tpr = &tp_s[qx][0][og*4];
                    while (m) {
                        int q = __ffsll(m) - 1;
                        m &= m - 1;
                        #pragma unroll
                        for (int kw = 0; kw < KK; kw++) {
                            int p2 = q - kw;
                            if ((unsigned)p2 < 32u) {
                                float4 tv = *reinterpret_cast<const float4*>(&tpr[p2*8]);
                                a[kw][0] += tv.x; a[kw][1] += tv.y;
                                a[kw][2] += tv.z; a[kw][3] += tv.w;
                            }
                        }
                    }
                }

                // Term B: spike-gated tr_pre sums (exact: s is 0/1).
                const float* urow = &trn[ii][qx + kh][0];
                #pragma unroll
                for (int c = 0; c < 4; c++) {
                    unsigned sm = smask[qx][og*4 + c];
                    while (sm) {
                        int p2 = __ffs(sm) - 1;
                        sm &= sm - 1;
                        #pragma unroll
                        for (int kw = 0; kw < KK; kw++)
                            a[kw][c] += urow[p2 + kw];
                    }
                }

                #pragma unroll
                for (int c = 0; c < 4; c++) {
                    const int o  = og*4 + c;
                    const int eb = ((o*CIN + ii)*KK + kh)*KK;
                    #pragma unroll
                    for (int kw = 0; kw < KK; kw++)
                        red[eb + kw][qx] = a[kw][c];
                }
            }
            __syncthreads();

            for (int e = tid; e < NW; e += 256) {
                float s = 0.f;
                #pragma unroll
                for (int j = 0; j < TH; j++) s += red[e][j];
                g_part[(size_t)e * NT + tile] = s;
            }
        }

        // ---- grid barrier #1 (phase A done) ----
        bar_target += (unsigned)ngrid;
        __syncthreads();
        if (tid == 0) {
            __threadfence();
            atomicAdd(&g_bar_count, 1u);
            while (*(volatile unsigned*)&g_bar_count < bar_target) __nanosleep(128);
            __threadfence();
        }
        __syncthreads();

        // ---- weight update (skipped exactly while no spike has ever fired) ----
        if (__ldcg(&g_anyact)) {
            if (bid < NW) {
                float s = 0.f;
                for (int j = tid; j < NT; j += 256)
                    s += __ldcg(&g_part[(size_t)bid * NT + j]);
                sbuf[tid] = s;
                __syncthreads();
                #pragma unroll
                for (int off = 128; off > 0; off >>= 1) {
                    if (tid < off) sbuf[tid] += sbuf[tid + off];
                    __syncthreads();
                }
                if (tid == 0)
                    g_w[bid] = __ldcg(&g_w[bid]) - 0.03f * sbuf[0];
            }
        }

        // ---- grid barrier #2 (weights published) ----
        bar_target += (unsigned)ngrid;
        __syncthreads();
        if (tid == 0) {
            __threadfence();
            atomicAdd(&g_bar_count, 1u);
            while (*(volatile unsigned*)&g_bar_count < bar_target) __nanosleep(128);
            __threadfence();
        }
        __syncthreads();
    }
}

extern "C" void kernel_launch(void* const* d_in, const int* in_sizes, int n_in,
                              void* d_out, int out_size) {
    const float* x = (const float*)d_in[0];
    const float* w = (const float*)d_in[1];
    if (in_sizes[0] == NW) {  // defensive: swap if metadata order is (weight, x_seq)
        x = (const float*)d_in[1];
        w = (const float*)d_in[0];
    }
    float* out = (float*)d_out;

    // Guaranteed-resident grid size for the software barrier.
    int perSM = 0, nsm = 0;
    cudaOccupancyMaxActiveBlocksPerMultiprocessor(&perSM, k_persist, 256, 0);
    cudaDeviceGetAttribute(&nsm, cudaDevAttrMultiProcessorCount, 0);
    int ngrid = perSM * nsm;
    if (ngrid > NT) ngrid = NT;
    if (ngrid < 1)  ngrid = 1;

    k_init<<<2048, 256>>>(w);
    k_persist<<<ngrid, 256>>>(x, out, ngrid);
}

// round 10
// speedup vs baseline: 1.0003x; 1.0003x over previous
#include <cuda_runtime.h>

// Problem dims
#define T_STEPS 32
#define NB      16
#define CIN     2
#define COUT    8
#define HH      128
#define WW      128
#define KK      5
#define PADL    2
#define HP      (HH + 2*PADL)   // 132
#define WP      (WW + 2*PADL)   // 132
#define NW      (COUT*CIN*KK*KK) // 400

// Tiling
#define TH 8
#define TW 32
#define PH (TH + 4)   // 12
#define PW 36         // halo window width (TW+4)
#define PW2 37        // trn padded width
#define NT ((WW/TW) * (HH/TH) * NB)   // 1024 tiles

// Persistent state (device globals: allocation-free)
__device__ float g_v[NB*COUT*HH*WW];          // membrane potential
__device__ float g_tp[NB*COUT*HH*WW];         // post trace
__device__ float g_trpre[2][NB*CIN*HP*WP];    // pre trace (padded grid), double buffered
__device__ float g_w[NW];                     // current weights
__device__ float g_part[NW * NT];             // per-tile dw partials
__device__ int   g_act[NB*2];                 // "any spike ever" per (batch, o-group)
__device__ int   g_anyact;                    // any spike ever, anywhere
__device__ unsigned g_bar_count;              // grid barrier ticket counter

__global__ void k_init(const float* __restrict__ w0) {
    int idx = blockIdx.x * blockDim.x + threadIdx.x;
    int stride = gridDim.x * blockDim.x;
    for (int i = idx; i < NB*COUT*HH*WW; i += stride) { g_v[i] = 0.f; g_tp[i] = 0.f; }
    for (int i = idx; i < NB*CIN*HP*WP; i += stride) { g_trpre[0][i] = 0.f; g_trpre[1][i] = 0.f; }
    if (idx < NW) g_w[idx] = w0[idx];
    if (idx < NB*2) g_act[idx] = 0;
    if (idx == 0) { g_anyact = 0; g_bar_count = 0u; }
}

// Persistent kernel: all T steps, software grid barrier between conv-phase
// and weight-update phase. Grid is sized by the host to guaranteed-resident
// block count, so the spin barrier cannot deadlock.
__global__ __launch_bounds__(256, 4)
void k_persist(const float* __restrict__ x_seq, float* __restrict__ out, int ngrid) {
    __shared__ float trn[CIN][PH][PW2];                 // NEW pre-trace patch
    __shared__ __align__(16) float tp_s[TH][TW][COUT];  // NEW post trace [row][col][o]
    __shared__ unsigned long long xmask[CIN][PH];       // x nonzero bitmask per halo row
    __shared__ unsigned int smask[TH][COUT];            // spike bitmask per (row, o)
    __shared__ __align__(16) float wt[50*COUT];         // weights transposed: [tap][o]
    __shared__ float red[NW][TH];                       // per-row dw partials
    __shared__ float sbuf[256];
    __shared__ int act_prior[2];

    const int tid = threadIdx.x;
    const int bid = blockIdx.x;
    unsigned bar_target = 0;

    for (int t = 0; t < T_STEPS; t++) {
        const int cur = t & 1;

        // Load weights transposed (L1-bypass: g_w updated by another block).
        for (int j = tid; j < NW; j += 256) {
            int o   = j / 50;
            int tap = j - o * 50;
            wt[tap*COUT + o] = __ldcg(&g_w[j]);
        }

        for (int tile = bid; tile < NT; tile += ngrid) {
            const int b   = tile >> 6;           // tile = tx + 4*(ty + 16*b)
            const int ty0 = ((tile >> 2) & 15) * TH;
            const int tx0 = (tile & 3) * TW;

            __syncthreads();   // smem reuse guard (prev tile / wt load done)
            if (tid < CIN*PH) ((unsigned long long*)xmask)[tid] = 0ull;
            if (tid < 2) act_prior[tid] = __ldcg(&g_act[b*2 + tid]);
            __syncthreads();

            const float* xt  = x_seq + (((size_t)t*NB + b) * CIN) * HH * WW;
            const float* tro = g_trpre[cur]     + (size_t)b * CIN * HP * WP;
            float*       trw = g_trpre[cur ^ 1] + (size_t)b * CIN * HP * WP;

            const int ownH = (ty0 + TH == HH) ? PH : TH;
            const int ownW = (tx0 + TW == WW) ? PW : TW;

            // Phase 0: pre-trace update + x bitmask build.
            for (int idx = tid; idx < CIN*PH*PW; idx += 256) {
                int i   = idx / (PH*PW);
                int rem = idx % (PH*PW);
                int r = rem / PW, c = rem % PW;
                int u = ty0 + r, vv = tx0 + c;
                int xr = u - PADL, xc = vv - PADL;
                float xv = 0.f;
                if (xr >= 0 && xr < HH && xc >= 0 && xc < WW)
                    xv = xt[(i*HH + xr)*WW + xc];
                float to = __ldcg(&tro[(i*HP + u)*WP + vv]);  // halo crosses blocks
                float tn = to - to / 30.0f + xv;
                trn[i][r][c] = tn;
                if (r < ownH && c < ownW)
                    trw[(i*HP + u)*WP + vv] = tn;
                if (xv != 0.f)
                    atomicOr(&xmask[i][r], 1ull << c);
            }
            __syncthreads();

            // Phase 1: sparse conv + LIF + traces + spike ballots.
            const int px = tid >> 5;
            const int py = tid & 31;
            int loc0, loc1;
            {
                float y[COUT];
                #pragma unroll
                for (int o = 0; o < COUT; o++) y[o] = 0.f;

                #pragma unroll
                for (int i = 0; i < CIN; i++) {
                    unsigned m = 0;
                    #pragma unroll
                    for (int kh = 0; kh < KK; kh++)
                        m |= (unsigned)((xmask[i][px + kh] >> py) & 0x1Full) << (kh*5);
                    while (m) {
                        int bpos = __ffs(m) - 1;
                        m &= m - 1;
                        const float* wp = &wt[(i*25 + bpos)*COUT];
                        float4 wa = *reinterpret_cast<const float4*>(wp);
                        float4 wb = *reinterpret_cast<const float4*>(wp + 4);
                        y[0] += wa.x; y[1] += wa.y; y[2] += wa.z; y[3] += wa.w;
                        y[4] += wb.x; y[5] += wb.y; y[6] += wb.z; y[7] += wb.w;
                    }
                }

                const int gx = ty0 + px, gy = tx0 + py;
                const size_t base = (size_t)b * COUT * HH * WW + (size_t)gx * WW + gy;
                float* outp = out + ((size_t)t * NB + b) * COUT * HH * WW + (size_t)gx * WW + gy;
                float tpv[COUT];
                unsigned ball[COUT];
                #pragma unroll
                for (int o = 0; o < COUT; o++) {
                    size_t gi = base + (size_t)o * HH * WW;
                    float v = g_v[gi];                     // tile-private (same SM)
                    v = v + (y[o] - v) / 100.0f;           // LIF charge
                    float s = (v >= 1.0f) ? 1.f : 0.f;     // fire
                    v = v * (1.f - s);                     // hard reset
                    g_v[gi] = v;
                    float tq = g_tp[gi];
                    tq = tq - tq / 30.0f + s;              // post trace
                    g_tp[gi] = tq;
                    outp[(size_t)o * HH * WW] = s;
                    tpv[o] = tq;
                    ball[o] = __ballot_sync(0xffffffffu, s != 0.f);
                    if (py == 0) smask[px][o] = ball[o];
                }
                *reinterpret_cast<float4*>(&tp_s[px][py][0]) = make_float4(tpv[0], tpv[1], tpv[2], tpv[3]);
                *reinterpret_cast<float4*>(&tp_s[px][py][4]) = make_float4(tpv[4], tpv[5], tpv[6], tpv[7]);
                loc0 = (ball[0] | ball[1] | ball[2] | ball[3]) != 0;
                loc1 = (ball[4] | ball[5] | ball[6] | ball[7]) != 0;
            }
            const int any0 = __syncthreads_or(loc0);
            const int any1 = __syncthreads_or(loc1);
            if (tid == 0) {
                if (any0 && !act_prior[0]) atomicOr(&g_act[b*2 + 0], 1);
                if (any1 && !act_prior[1]) atomicOr(&g_act[b*2 + 1], 1);
                if (any0 | any1) atomicOr(&g_anyact, 1);
            }

            // Phase 2: sparse dw partials. 160 threads = (px:8) x (og:2, ii:2, kh:5).
            if (tid < 160) {
                const int qx = tid / 20;
                const int g  = tid - qx * 20;
                const int og = g & 1;
                const int ii = (g >> 1) & 1;
                const int kh = g >> 2;

                float a[KK][4];
                #pragma unroll
                for (int kw = 0; kw < KK; kw++)
                    #pragma unroll
                    for (int c = 0; c < 4; c++) a[kw][c] = 0.f;

                // Term A: tp (x) correlation — exact skip while tp == 0.
                const int act = og ? (act_prior[1] | any1) : (act_prior[0] | any0);
                if (act) {
                    unsigned long long m = xmask[ii][qx + kh];
                    const float* tpr = &tp_s[qx][0][og*4];
                    while (m) {
                        int q = __ffsll(m) - 1;
                        m &= m - 1;
                        #pragma unroll
                        for (int kw = 0; kw < KK; kw++) {
                            int p2 = q - kw;
                            if ((unsigned)p2 < 32u) {
                                float4 tv = *reinterpret_cast<const float4*>(&tpr[p2*8]);
                                a[kw][0] += tv.x; a[kw][1] += tv.y;
                                a[kw][2] += tv.z; a[kw][3] += tv.w;
                            }
                        }
                    }
                }

                // Term B: spike-gated tr_pre sums (exact: s is 0/1).
                const float* urow = &trn[ii][qx + kh][0];
                #pragma unroll
                for (int c = 0; c < 4; c++) {
                    unsigned sm = smask[qx][og*4 + c];
                    while (sm) {
                        int p2 = __ffs(sm) - 1;
                        sm &= sm - 1;
                        #pragma unroll
                        for (int kw = 0; kw < KK; kw++)
                            a[kw][c] += urow[p2 + kw];
                    }
                }

                #pragma unroll
                for (int c = 0; c < 4; c++) {
                    const int o  = og*4 + c;
                    const int eb = ((o*CIN + ii)*KK + kh)*KK;
                    #pragma unroll
                    for (int kw = 0; kw < KK; kw++)
                        red[eb + kw][qx] = a[kw][c];
                }
            }
            __syncthreads();

            for (int e = tid; e < NW; e += 256) {
                float s = 0.f;
                #pragma unroll
                for (int j = 0; j < TH; j++) s += red[e][j];
                g_part[(size_t)e * NT + tile] = s;
            }
        }

        // ---- grid barrier #1 (phase A done) ----
        bar_target += (unsigned)ngrid;
        __syncthreads();
        if (tid == 0) {
            __threadfence();
            atomicAdd(&g_bar_count, 1u);
            while (*(volatile unsigned*)&g_bar_count < bar_target) __nanosleep(128);
            __threadfence();
        }
        __syncthreads();

        // ---- weight update (skipped exactly while no spike has ever fired) ----
        if (__ldcg(&g_anyact)) {
            if (bid < NW) {
                float s = 0.f;
                for (int j = tid; j < NT; j += 256)
                    s += __ldcg(&g_part[(size_t)bid * NT + j]);
                sbuf[tid] = s;
                __syncthreads();
                #pragma unroll
                for (int off = 128; off > 0; off >>= 1) {
                    if (tid < off) sbuf[tid] += sbuf[tid + off];
                    __syncthreads();
                }
                if (tid == 0)
                    g_w[bid] = __ldcg(&g_w[bid]) - 0.03f * sbuf[0];
            }
        }

        // ---- grid barrier #2 (weights published) ----
        bar_target += (unsigned)ngrid;
        __syncthreads();
        if (tid == 0) {
            __threadfence();
            atomicAdd(&g_bar_count, 1u);
            while (*(volatile unsigned*)&g_bar_count < bar_target) __nanosleep(128);
            __threadfence();
        }
        __syncthreads();
    }
}

extern "C" void kernel_launch(void* const* d_in, const int* in_sizes, int n_in,
                              void* d_out, int out_size) {
    const float* x = (const float*)d_in[0];
    const float* w = (const float*)d_in[1];
    if (in_sizes[0] == NW) {  // defensive: swap if metadata order is (weight, x_seq)
        x = (const float*)d_in[1];
        w = (const float*)d_in[0];
    }
    float* out = (float*)d_out;

    // Guaranteed-resident grid size for the software barrier.
    int perSM = 0, nsm = 0;
    cudaOccupancyMaxActiveBlocksPerMultiprocessor(&perSM, k_persist, 256, 0);
    cudaDeviceGetAttribute(&nsm, cudaDevAttrMultiProcessorCount, 0);
    int ngrid = perSM * nsm;
    if (ngrid > NT) ngrid = NT;
    if (ngrid < 1)  ngrid = 1;

    k_init<<<2048, 256>>>(w);
    k_persist<<<ngrid, 256>>>(x, out, ngrid);
}

// round 11
// speedup vs baseline: 1.0039x; 1.0036x over previous
#include <cuda_runtime.h>

// Problem dims
#define T_STEPS 32
#define NB      16
#define CIN     2
#define COUT    8
#define HH      128
#define WW      128
#define KK      5
#define PADL    2
#define HP      (HH + 2*PADL)   // 132
#define WP      (WW + 2*PADL)   // 132
#define NW      (COUT*CIN*KK*KK) // 400

// Tiling
#define TH 8
#define TW 32
#define PH (TH + 4)   // 12
#define PW 36         // halo window width (TW+4)
#define PW2 37        // trn padded width
#define NT ((WW/TW) * (HH/TH) * NB)   // 1024 tiles

// Persistent state (device globals: allocation-free)
__device__ float g_v[NB*COUT*HH*WW];          // membrane potential
__device__ float g_tp[NB*COUT*HH*WW];         // post trace
__device__ float g_trpre[2][NB*CIN*HP*WP];    // pre trace (padded grid), double buffered
__device__ float g_w[NW];                     // current weights
__device__ float g_part[NW * NT];             // per-tile dw partials
__device__ int   g_act[NB*2];                 // "any spike ever" per (batch, o-group)
__device__ int   g_anyact;                    // any spike ever, anywhere
__device__ unsigned g_bar_count;              // grid barrier ticket counter

__global__ void k_init(const float* __restrict__ w0) {
    int idx = blockIdx.x * blockDim.x + threadIdx.x;
    int stride = gridDim.x * blockDim.x;
    for (int i = idx; i < NB*COUT*HH*WW; i += stride) { g_v[i] = 0.f; g_tp[i] = 0.f; }
    for (int i = idx; i < NB*CIN*HP*WP; i += stride) { g_trpre[0][i] = 0.f; g_trpre[1][i] = 0.f; }
    if (idx < NW) g_w[idx] = w0[idx];
    if (idx < NB*2) g_act[idx] = 0;
    if (idx == 0) { g_anyact = 0; g_bar_count = 0u; }
}

// Persistent kernel: all T steps, software grid barrier between conv-phase
// and weight-update phase. Grid is sized by the host to guaranteed-resident
// block count, so the spin barrier cannot deadlock.
__global__ __launch_bounds__(256, 4)
void k_persist(const float* __restrict__ x_seq, float* __restrict__ out, int ngrid) {
    __shared__ float trn[CIN][PH][PW2];                 // NEW pre-trace patch
    __shared__ __align__(16) float tp_s[TH][TW][COUT];  // NEW post trace [row][col][o]
    __shared__ unsigned long long xmask[CIN][PH];       // x nonzero bitmask per halo row
    __shared__ unsigned int smask[TH][COUT];            // spike bitmask per (row, o)
    __shared__ __align__(16) float wt[50*COUT];         // weights transposed: [tap][o]
    __shared__ float red[NW][TH];                       // per-row dw partials
    __shared__ float sbuf[256];
    __shared__ int act_prior[2];

    const int tid = threadIdx.x;
    const int bid = blockIdx.x;
    unsigned bar_target = 0;

    for (int t = 0; t < T_STEPS; t++) {
        const int cur = t & 1;

        // Load weights transposed (L1-bypass: g_w updated by another block).
        for (int j = tid; j < NW; j += 256) {
            int o   = j / 50;
            int tap = j - o * 50;
            wt[tap*COUT + o] = __ldcg(&g_w[j]);
        }

        for (int tile = bid; tile < NT; tile += ngrid) {
            const int b   = tile >> 6;           // tile = tx + 4*(ty + 16*b)
            const int ty0 = ((tile >> 2) & 15) * TH;
            const int tx0 = (tile & 3) * TW;

            __syncthreads();   // smem reuse guard (prev tile / wt load done)
            if (tid < CIN*PH) ((unsigned long long*)xmask)[tid] = 0ull;
            if (tid < 2) act_prior[tid] = __ldcg(&g_act[b*2 + tid]);
            __syncthreads();

            const float* xt  = x_seq + (((size_t)t*NB + b) * CIN) * HH * WW;
            const float* tro = g_trpre[cur]     + (size_t)b * CIN * HP * WP;
            float*       trw = g_trpre[cur ^ 1] + (size_t)b * CIN * HP * WP;

            const int ownH = (ty0 + TH == HH) ? PH : TH;
            const int ownW = (tx0 + TW == WW) ? PW : TW;

            // Phase 0: pre-trace update + x bitmask build.
            for (int idx = tid; idx < CIN*PH*PW; idx += 256) {
                int i   = idx / (PH*PW);
                int rem = idx % (PH*PW);
                int r = rem / PW, c = rem % PW;
                int u = ty0 + r, vv = tx0 + c;
                int xr = u - PADL, xc = vv - PADL;
                float xv = 0.f;
                if (xr >= 0 && xr < HH && xc >= 0 && xc < WW)
                    xv = xt[(i*HH + xr)*WW + xc];
                float to = __ldcg(&tro[(i*HP + u)*WP + vv]);  // halo crosses blocks
                float tn = to - to / 30.0f + xv;
                trn[i][r][c] = tn;
                if (r < ownH && c < ownW)
                    trw[(i*HP + u)*WP + vv] = tn;
                if (xv != 0.f)
                    atomicOr(&xmask[i][r], 1ull << c);
            }
            __syncthreads();

            // Phase 1: sparse conv + LIF + traces + spike ballots.
            const int px = tid >> 5;
            const int py = tid & 31;
            int loc0, loc1;
            {
                float y[COUT];
                #pragma unroll
                for (int o = 0; o < COUT; o++) y[o] = 0.f;

                #pragma unroll
                for (int i = 0; i < CIN; i++) {
                    unsigned m = 0;
                    #pragma unroll
                    for (int kh = 0; kh < KK; kh++)
                        m |= (unsigned)((xmask[i][px + kh] >> py) & 0x1Full) << (kh*5);
                    while (m) {
                        int bpos = __ffs(m) - 1;
                        m &= m - 1;
                        const float* wp = &wt[(i*25 + bpos)*COUT];
                        float4 wa = *reinterpret_cast<const float4*>(wp);
                        float4 wb = *reinterpret_cast<const float4*>(wp + 4);
                        y[0] += wa.x; y[1] += wa.y; y[2] += wa.z; y[3] += wa.w;
                        y[4] += wb.x; y[5] += wb.y; y[6] += wb.z; y[7] += wb.w;
                    }
                }

                const int gx = ty0 + px, gy = tx0 + py;
                const size_t base = (size_t)b * COUT * HH * WW + (size_t)gx * WW + gy;
                float* outp = out + ((size_t)t * NB + b) * COUT * HH * WW + (size_t)gx * WW + gy;
                float tpv[COUT];
                unsigned ball[COUT];
                #pragma unroll
                for (int o = 0; o < COUT; o++) {
                    size_t gi = base + (size_t)o * HH * WW;
                    float v = g_v[gi];                     // tile-private (same SM)
                    v = v + (y[o] - v) / 100.0f;           // LIF charge
                    float s = (v >= 1.0f) ? 1.f : 0.f;     // fire
                    v = v * (1.f - s);                     // hard reset
                    g_v[gi] = v;
                    float tq = g_tp[gi];
                    tq = tq - tq / 30.0f + s;              // post trace
                    g_tp[gi] = tq;
                    outp[(size_t)o * HH * WW] = s;
                    tpv[o] = tq;
                    ball[o] = __ballot_sync(0xffffffffu, s != 0.f);
                    if (py == 0) smask[px][o] = ball[o];
                }
                *reinterpret_cast<float4*>(&tp_s[px][py][0]) = make_float4(tpv[0], tpv[1], tpv[2], tpv[3]);
                *reinterpret_cast<float4*>(&tp_s[px][py][4]) = make_float4(tpv[4], tpv[5], tpv[6], tpv[7]);
                loc0 = (ball[0] | ball[1] | ball[2] | ball[3]) != 0;
                loc1 = (ball[4] | ball[5] | ball[6] | ball[7]) != 0;
            }
            const int any0 = __syncthreads_or(loc0);
            const int any1 = __syncthreads_or(loc1);
            if (tid == 0) {
                if (any0 && !act_prior[0]) atomicOr(&g_act[b*2 + 0], 1);
                if (any1 && !act_prior[1]) atomicOr(&g_act[b*2 + 1], 1);
                if (any0 | any1) atomicOr(&g_anyact, 1);
            }

            // Phase 2: sparse dw partials. 160 threads = (px:8) x (og:2, ii:2, kh:5).
            if (tid < 160) {
                const int qx = tid / 20;
                const int g  = tid - qx * 20;
                const int og = g & 1;
                const int ii = (g >> 1) & 1;
                const int kh = g >> 2;

                float a[KK][4];
                #pragma unroll
                for (int kw = 0; kw < KK; kw++)
                    #pragma unroll
                    for (int c = 0; c < 4; c++) a[kw][c] = 0.f;

                // Term A: tp (x) correlation — exact skip while tp == 0.
                const int act = og ? (act_prior[1] | any1) : (act_prior[0] | any0);
                if (act) {
                    unsigned long long m = xmask[ii][qx + kh];
                    const float* tpr = &tp_s[qx][0][og*4];
                    while (m) {
                        int q = __ffsll(m) - 1;
                        m &= m - 1;
                        #pragma unroll
                        for (int kw = 0; kw < KK; kw++) {
                            int p2 = q - kw;
                            if ((unsigned)p2 < 32u) {
                                float4 tv = *reinterpret_cast<const float4*>(&tpr[p2*8]);
                                a[kw][0] += tv.x; a[kw][1] += tv.y;
                                a[kw][2] += tv.z; a[kw][3] += tv.w;
                            }
                        }
                    }
                }

                // Term B: spike-gated tr_pre sums (exact: s is 0/1).
                const float* urow = &trn[ii][qx + kh][0];
                #pragma unroll
                for (int c = 0; c < 4; c++) {
                    unsigned sm = smask[qx][og*4 + c];
                    while (sm) {
                        int p2 = __ffs(sm) - 1;
                        sm &= sm - 1;
                        #pragma unroll
                        for (int kw = 0; kw < KK; kw++)
                            a[kw][c] += urow[p2 + kw];
                    }
                }

                #pragma unroll
                for (int c = 0; c < 4; c++) {
                    const int o  = og*4 + c;
                    const int eb = ((o*CIN + ii)*KK + kh)*KK;
                    #pragma unroll
                    for (int kw = 0; kw < KK; kw++)
                        red[eb + kw][qx] = a[kw][c];
                }
            }
            __syncthreads();

            for (int e = tid; e < NW; e += 256) {
                float s = 0.f;
                #pragma unroll
                for (int j = 0; j < TH; j++) s += red[e][j];
                g_part[(size_t)e * NT + tile] = s;
            }
        }

        // ---- grid barrier #1 (phase A done) ----
        bar_target += (unsigned)ngrid;
        __syncthreads();
        if (tid == 0) {
            __threadfence();
            atomicAdd(&g_bar_count, 1u);
            while (*(volatile unsigned*)&g_bar_count < bar_target) __nanosleep(128);
            __threadfence();
        }
        __syncthreads();

        // ---- weight update (skipped exactly while no spike has ever fired) ----
        if (__ldcg(&g_anyact)) {
            if (bid < NW) {
                float s = 0.f;
                for (int j = tid; j < NT; j += 256)
                    s += __ldcg(&g_part[(size_t)bid * NT + j]);
                sbuf[tid] = s;
                __syncthreads();
                #pragma unroll
                for (int off = 128; off > 0; off >>= 1) {
                    if (tid < off) sbuf[tid] += sbuf[tid + off];
                    __syncthreads();
                }
                if (tid == 0)
                    g_w[bid] = __ldcg(&g_w[bid]) - 0.03f * sbuf[0];
            }
        }

        // ---- grid barrier #2 (weights published) ----
        bar_target += (unsigned)ngrid;
        __syncthreads();
        if (tid == 0) {
            __threadfence();
            atomicAdd(&g_bar_count, 1u);
            while (*(volatile unsigned*)&g_bar_count < bar_target) __nanosleep(128);
            __threadfence();
        }
        __syncthreads();
    }
}

extern "C" void kernel_launch(void* const* d_in, const int* in_sizes, int n_in,
                              void* d_out, int out_size) {
    const float* x = (const float*)d_in[0];
    const float* w = (const float*)d_in[1];
    if (in_sizes[0] == NW) {  // defensive: swap if metadata order is (weight, x_seq)
        x = (const float*)d_in[1];
        w = (const float*)d_in[0];
    }
    float* out = (float*)d_out;

    // Guaranteed-resident grid size for the software barrier.
    int perSM = 0, nsm = 0;
    cudaOccupancyMaxActiveBlocksPerMultiprocessor(&perSM, k_persist, 256, 0);
    cudaDeviceGetAttribute(&nsm, cudaDevAttrMultiProcessorCount, 0);
    int ngrid = perSM * nsm;
    if (ngrid > NT) ngrid = NT;
    if (ngrid < 1)  ngrid = 1;

    k_init<<<2048, 256>>>(w);
    k_persist<<<ngrid, 256>>>(x, out, ngrid);
}

// round 12
// speedup vs baseline: 1.0053x; 1.0014x over previous
#include <cuda_runtime.h>

// Problem dims
#define T_STEPS 32
#define NB      16
#define CIN     2
#define COUT    8
#define HH      128
#define WW      128
#define KK      5
#define PADL    2
#define HP      (HH + 2*PADL)   // 132
#define WP      (WW + 2*PADL)   // 132
#define NW      (COUT*CIN*KK*KK) // 400

// Tiling
#define TH 8
#define TW 32
#define PH (TH + 4)   // 12
#define PW 36         // halo window width (TW+4)
#define PW2 37        // trn padded width
#define NT ((WW/TW) * (HH/TH) * NB)   // 1024 tiles

// Persistent state (device globals: allocation-free)
__device__ float g_v[NB*COUT*HH*WW];          // membrane potential
__device__ float g_tp[NB*COUT*HH*WW];         // post trace
__device__ float g_trpre[2][NB*CIN*HP*WP];    // pre trace (padded grid), double buffered
__device__ float g_w[NW];                     // current weights
__device__ float g_part[NW * NT];             // per-tile dw partials
__device__ int   g_act[NB*2];                 // "any spike ever" per (batch, o-group)
__device__ int   g_anyact;                    // any spike ever, anywhere
__device__ unsigned g_bar_count;              // grid barrier ticket counter

__global__ void k_init(const float* __restrict__ w0) {
    int idx = blockIdx.x * blockDim.x + threadIdx.x;
    int stride = gridDim.x * blockDim.x;
    for (int i = idx; i < NB*COUT*HH*WW; i += stride) { g_v[i] = 0.f; g_tp[i] = 0.f; }
    for (int i = idx; i < NB*CIN*HP*WP; i += stride) { g_trpre[0][i] = 0.f; g_trpre[1][i] = 0.f; }
    if (idx < NW) g_w[idx] = w0[idx];
    if (idx < NB*2) g_act[idx] = 0;
    if (idx == 0) { g_anyact = 0; g_bar_count = 0u; }
}

// Persistent kernel: all T steps, software grid barrier between conv-phase
// and weight-update phase. Grid is sized by the host to guaranteed-resident
// block count, so the spin barrier cannot deadlock.
__global__ __launch_bounds__(256, 4)
void k_persist(const float* __restrict__ x_seq, float* __restrict__ out, int ngrid) {
    __shared__ float trn[CIN][PH][PW2];                 // NEW pre-trace patch
    __shared__ __align__(16) float tp_s[TH][TW][COUT];  // NEW post trace [row][col][o]
    __shared__ unsigned long long xmask[CIN][PH];       // x nonzero bitmask per halo row
    __shared__ unsigned int smask[TH][COUT];            // spike bitmask per (row, o)
    __shared__ __align__(16) float wt[50*COUT];         // weights transposed: [tap][o]
    __shared__ float red[NW][TH];                       // per-row dw partials
    __shared__ float sbuf[256];
    __shared__ int act_prior[2];

    const int tid = threadIdx.x;
    const int bid = blockIdx.x;
    unsigned bar_target = 0;

    for (int t = 0; t < T_STEPS; t++) {
        const int cur = t & 1;

        // Load weights transposed (L1-bypass: g_w updated by another block).
        for (int j = tid; j < NW; j += 256) {
            int o   = j / 50;
            int tap = j - o * 50;
            wt[tap*COUT + o] = __ldcg(&g_w[j]);
        }

        for (int tile = bid; tile < NT; tile += ngrid) {
            const int b   = tile >> 6;           // tile = tx + 4*(ty + 16*b)
            const int ty0 = ((tile >> 2) & 15) * TH;
            const int tx0 = (tile & 3) * TW;

            __syncthreads();   // smem reuse guard (prev tile / wt load done)
            if (tid < CIN*PH) ((unsigned long long*)xmask)[tid] = 0ull;
            if (tid < 2) act_prior[tid] = __ldcg(&g_act[b*2 + tid]);
            __syncthreads();

            const float* xt  = x_seq + (((size_t)t*NB + b) * CIN) * HH * WW;
            const float* tro = g_trpre[cur]     + (size_t)b * CIN * HP * WP;
            float*       trw = g_trpre[cur ^ 1] + (size_t)b * CIN * HP * WP;

            const int ownH = (ty0 + TH == HH) ? PH : TH;
            const int ownW = (tx0 + TW == WW) ? PW : TW;

            // Phase 0: pre-trace update + x bitmask build.
            for (int idx = tid; idx < CIN*PH*PW; idx += 256) {
                int i   = idx / (PH*PW);
                int rem = idx % (PH*PW);
                int r = rem / PW, c = rem % PW;
                int u = ty0 + r, vv = tx0 + c;
                int xr = u - PADL, xc = vv - PADL;
                float xv = 0.f;
                if (xr >= 0 && xr < HH && xc >= 0 && xc < WW)
                    xv = xt[(i*HH + xr)*WW + xc];
                float to = __ldcg(&tro[(i*HP + u)*WP + vv]);  // halo crosses blocks
                float tn = to - to / 30.0f + xv;
                trn[i][r][c] = tn;
                if (r < ownH && c < ownW)
                    trw[(i*HP + u)*WP + vv] = tn;
                if (xv != 0.f)
                    atomicOr(&xmask[i][r], 1ull << c);
            }
            __syncthreads();

            // Phase 1: sparse conv + LIF + traces + spike ballots.
            const int px = tid >> 5;
            const int py = tid & 31;
            int loc0, loc1;
            {
                float y[COUT];
                #pragma unroll
                for (int o = 0; o < COUT; o++) y[o] = 0.f;

                #pragma unroll
                for (int i = 0; i < CIN; i++) {
                    unsigned m = 0;
                    #pragma unroll
                    for (int kh = 0; kh < KK; kh++)
                        m |= (unsigned)((xmask[i][px + kh] >> py) & 0x1Full) << (kh*5);
                    while (m) {
                        int bpos = __ffs(m) - 1;
                        m &= m - 1;
                        const float* wp = &wt[(i*25 + bpos)*COUT];
                        float4 wa = *reinterpret_cast<const float4*>(wp);
                        float4 wb = *reinterpret_cast<const float4*>(wp + 4);
                        y[0] += wa.x; y[1] += wa.y; y[2] += wa.z; y[3] += wa.w;
                        y[4] += wb.x; y[5] += wb.y; y[6] += wb.z; y[7] += wb.w;
                    }
                }

                const int gx = ty0 + px, gy = tx0 + py;
                const size_t base = (size_t)b * COUT * HH * WW + (size_t)gx * WW + gy;
                float* outp = out + ((size_t)t * NB + b) * COUT * HH * WW + (size_t)gx * WW + gy;
                float tpv[COUT];
                unsigned ball[COUT];
                #pragma unroll
                for (int o = 0; o < COUT; o++) {
                    size_t gi = base + (size_t)o * HH * WW;
                    float v = g_v[gi];                     // tile-private (same SM)
                    v = v + (y[o] - v) / 100.0f;           // LIF charge
                    float s = (v >= 1.0f) ? 1.f : 0.f;     // fire
                    v = v * (1.f - s);                     // hard reset
                    g_v[gi] = v;
                    float tq = g_tp[gi];
                    tq = tq - tq / 30.0f + s;              // post trace
                    g_tp[gi] = tq;
                    outp[(size_t)o * HH * WW] = s;
                    tpv[o] = tq;
                    ball[o] = __ballot_sync(0xffffffffu, s != 0.f);
                    if (py == 0) smask[px][o] = ball[o];
                }
                *reinterpret_cast<float4*>(&tp_s[px][py][0]) = make_float4(tpv[0], tpv[1], tpv[2], tpv[3]);
                *reinterpret_cast<float4*>(&tp_s[px][py][4]) = make_float4(tpv[4], tpv[5], tpv[6], tpv[7]);
                loc0 = (ball[0] | ball[1] | ball[2] | ball[3]) != 0;
                loc1 = (ball[4] | ball[5] | ball[6] | ball[7]) != 0;
            }
            const int any0 = __syncthreads_or(loc0);
            const int any1 = __syncthreads_or(loc1);
            if (tid == 0) {
                if (any0 && !act_prior[0]) atomicOr(&g_act[b*2 + 0], 1);
                if (any1 && !act_prior[1]) atomicOr(&g_act[b*2 + 1], 1);
                if (any0 | any1) atomicOr(&g_anyact, 1);
            }

            // Phase 2: sparse dw partials. 160 threads = (px:8) x (og:2, ii:2, kh:5).
            if (tid < 160) {
                const int qx = tid / 20;
                const int g  = tid - qx * 20;
                const int og = g & 1;
                const int ii = (g >> 1) & 1;
                const int kh = g >> 2;

                float a[KK][4];
                #pragma unroll
                for (int kw = 0; kw < KK; kw++)
                    #pragma unroll
                    for (int c = 0; c < 4; c++) a[kw][c] = 0.f;

                // Term A: tp (x) correlation — exact skip while tp == 0.
                const int act = og ? (act_prior[1] | any1) : (act_prior[0] | any0);
                if (act) {
                    unsigned long long m = xmask[ii][qx + kh];
                    const float* tpr = &tp_s[qx][0][og*4];
                    while (m) {
                        int q = __ffsll(m) - 1;
                        m &= m - 1;
                        #pragma unroll
                        for (int kw = 0; kw < KK; kw++) {
                            int p2 = q - kw;
                            if ((unsigned)p2 < 32u) {
                                float4 tv = *reinterpret_cast<const float4*>(&tpr[p2*8]);
                                a[kw][0] += tv.x; a[kw][1] += tv.y;
                                a[kw][2] += tv.z; a[kw][3] += tv.w;
                            }
                        }
                    }
                }

                // Term B: spike-gated tr_pre sums (exact: s is 0/1).
                const float* urow = &trn[ii][qx + kh][0];
                #pragma unroll
                for (int c = 0; c < 4; c++) {
                    unsigned sm = smask[qx][og*4 + c];
                    while (sm) {
                        int p2 = __ffs(sm) - 1;
                        sm &= sm - 1;
                        #pragma unroll
                        for (int kw = 0; kw < KK; kw++)
                            a[kw][c] += urow[p2 + kw];
                    }
                }

                #pragma unroll
                for (int c = 0; c < 4; c++) {
                    const int o  = og*4 + c;
                    const int eb = ((o*CIN + ii)*KK + kh)*KK;
                    #pragma unroll
                    for (int kw = 0; kw < KK; kw++)
                        red[eb + kw][qx] = a[kw][c];
                }
            }
            __syncthreads();

            for (int e = tid; e < NW; e += 256) {
                float s = 0.f;
                #pragma unroll
                for (int j = 0; j < TH; j++) s += red[e][j];
                g_part[(size_t)e * NT + tile] = s;
            }
        }

        // ---- grid barrier #1 (phase A done) ----
        bar_target += (unsigned)ngrid;
        __syncthreads();
        if (tid == 0) {
            __threadfence();
            atomicAdd(&g_bar_count, 1u);
            while (*(volatile unsigned*)&g_bar_count < bar_target) __nanosleep(128);
            __threadfence();
        }
        __syncthreads();

        // ---- weight update (skipped exactly while no spike has ever fired) ----
        if (__ldcg(&g_anyact)) {
            if (bid < NW) {
                float s = 0.f;
                for (int j = tid; j < NT; j += 256)
                    s += __ldcg(&g_part[(size_t)bid * NT + j]);
                sbuf[tid] = s;
                __syncthreads();
                #pragma unroll
                for (int off = 128; off > 0; off >>= 1) {
                    if (tid < off) sbuf[tid] += sbuf[tid + off];
                    __syncthreads();
                }
                if (tid == 0)
                    g_w[bid] = __ldcg(&g_w[bid]) - 0.03f * sbuf[0];
            }
        }

        // ---- grid barrier #2 (weights published) ----
        bar_target += (unsigned)ngrid;
        __syncthreads();
        if (tid == 0) {
            __threadfence();
            atomicAdd(&g_bar_count, 1u);
            while (*(volatile unsigned*)&g_bar_count < bar_target) __nanosleep(128);
            __threadfence();
        }
        __syncthreads();
    }
}

extern "C" void kernel_launch(void* const* d_in, const int* in_sizes, int n_in,
                              void* d_out, int out_size) {
    const float* x = (const float*)d_in[0];
    const float* w = (const float*)d_in[1];
    if (in_sizes[0] == NW) {  // defensive: swap if metadata order is (weight, x_seq)
        x = (const float*)d_in[1];
        w = (const float*)d_in[0];
    }
    float* out = (float*)d_out;

    // Guaranteed-resident grid size for the software barrier.
    int perSM = 0, nsm = 0;
    cudaOccupancyMaxActiveBlocksPerMultiprocessor(&perSM, k_persist, 256, 0);
    cudaDeviceGetAttribute(&nsm, cudaDevAttrMultiProcessorCount, 0);
    int ngrid = perSM * nsm;
    if (ngrid > NT) ngrid = NT;
    if (ngrid < 1)  ngrid = 1;

    k_init<<<2048, 256>>>(w);
    k_persist<<<ngrid, 256>>>(x, out, ngrid);
}

// round 13
// speedup vs baseline: 5.0950x; 5.0681x over previous
#include <cuda_runtime.h>
#include <climits>

// Problem dims
#define T_STEPS 32
#define NB      16
#define CIN     2
#define COUT    8
#define HH      128
#define WW      128
#define KK      5
#define PADL    2
#define HP      (HH + 2*PADL)   // 132
#define WP      (WW + 2*PADL)   // 132
#define NW      (COUT*CIN*KK*KK) // 400

// Tiling
#define TH 8
#define TW 32
#define PH (TH + 4)   // 12
#define PW 36
#define PW2 37
#define NT ((WW/TW) * (HH/TH) * NB)   // 1024 tiles
#define NROWS (T_STEPS*NB*CIN*HH)     // 131072 mask rows

// Persistent state (device globals: allocation-free)
__device__ float g_v[NB*COUT*HH*WW];
__device__ float g_tp[NB*COUT*HH*WW];
__device__ float g_trpre[2][NB*CIN*HP*WP];
__device__ float g_w[NW];
__device__ float g_part[NW * NT];
__device__ int   g_act[NB*2];
__device__ int   g_anyact;
__device__ unsigned g_bar_count;
__device__ ulonglong2 g_xm[NROWS];    // 128-bit x row masks, 2MB
__device__ int   g_first;             // first spike step anywhere, or INT_MAX

__global__ void k_init(const float* __restrict__ w0) {
    int idx = threadIdx.x;
    if (idx < NW) g_w[idx] = w0[idx];
    if (idx < NB*2) g_act[idx] = 0;
    if (idx == 0) { g_anyact = 0; g_bar_count = 0u; g_first = INT_MAX; }
}

// Pass 0: build binary x masks for all (t, b, i, row).
__global__ void k_masks(const float* __restrict__ x) {
    const int nwarps = (gridDim.x * blockDim.x) >> 5;
    const int wid = (blockIdx.x * blockDim.x + threadIdx.x) >> 5;
    const int l = threadIdx.x & 31;
    for (int row = wid; row < NROWS; row += nwarps) {
        const float* xr = x + (size_t)row * WW;
        unsigned b0 = __ballot_sync(0xffffffffu, xr[l       ] != 0.f);
        unsigned b1 = __ballot_sync(0xffffffffu, xr[l + 32  ] != 0.f);
        unsigned b2 = __ballot_sync(0xffffffffu, xr[l + 64  ] != 0.f);
        unsigned b3 = __ballot_sync(0xffffffffu, xr[l + 96  ] != 0.f);
        if (l == 0)
            g_xm[row] = make_ulonglong2(b0 | ((unsigned long long)b1 << 32),
                                        b2 | ((unsigned long long)b3 << 32));
    }
}

// Pass 1 (speculative fast path): per-tile fully-local simulation, weights
// fixed at w0. Exact while no spike occurs anywhere (then dw == 0 exactly and
// traces are unobservable). Records the earliest spike step in g_first.
__global__ __launch_bounds__(256)
void k_fast(float* __restrict__ out) {
    __shared__ __align__(16) float wt[50*COUT];   // weights transposed [tap][o]
    __shared__ unsigned long long xm[CIN][PH];

    const int tid = threadIdx.x;
    for (int j = tid; j < NW; j += 256) {
        int o = j / 50, tap = j - o * 50;
        wt[tap*COUT + o] = g_w[j];                 // == w0 for this whole pass
    }
    const int px = tid >> 5;
    const int py = tid & 31;

    for (int tile = blockIdx.x; tile < NT; tile += gridDim.x) {
        const int b   = tile >> 6;
        const int ty0 = ((tile >> 2) & 15) * TH;
        const int tx0 = (tile & 3) * TW;
        const int gx = ty0 + px, gy = tx0 + py;

        float v[COUT];
        #pragma unroll
        for (int o = 0; o < COUT; o++) v[o] = 0.f;

        int firstloc = INT_MAX;
        for (int t = 0; t < T_STEPS; t++) {
            __syncthreads();
            if (tid < CIN*PH) {
                const int i = tid / PH, r = tid - i*PH;
                const int xr = ty0 - PADL + r;
                unsigned long long win = 0ull;
                if ((unsigned)xr < (unsigned)HH) {
                    ulonglong2 m = g_xm[((t*NB + b)*CIN + i)*HH + xr];
                    if (tx0 == 0) win = m.x << 2;
                    else {
                        int s = tx0 - PADL;        // 30, 62, 94
                        win = (s < 64) ? ((m.x >> s) | (m.y << (64 - s)))
                                       : (m.y >> (s - 64));
                    }
                    win &= (1ull << 36) - 1;
                }
                xm[i][r] = win;
            }
            __syncthreads();

            float y[COUT];
            #pragma unroll
            for (int o = 0; o < COUT; o++) y[o] = 0.f;
            #pragma unroll
            for (int i = 0; i < CIN; i++) {
                unsigned m = 0;
                #pragma unroll
                for (int kh = 0; kh < KK; kh++)
                    m |= (unsigned)((xm[i][px + kh] >> py) & 0x1Full) << (kh*5);
                while (m) {
                    int bp = __ffs(m) - 1;
                    m &= m - 1;
                    const float* wp = &wt[(i*25 + bp)*COUT];
                    float4 wa = *reinterpret_cast<const float4*>(wp);
                    float4 wb = *reinterpret_cast<const float4*>(wp + 4);
                    y[0] += wa.x; y[1] += wa.y; y[2] += wa.z; y[3] += wa.w;
                    y[4] += wb.x; y[5] += wb.y; y[6] += wb.z; y[7] += wb.w;
                }
            }

            float* outp = out + ((size_t)t*NB + b)*COUT*HH*WW + (size_t)gx*WW + gy;
            float anys = 0.f;
            #pragma unroll
            for (int o = 0; o < COUT; o++) {
                float vv = v[o] + (y[o] - v[o]) / 100.0f;   // LIF charge
                float s  = (vv >= 1.0f) ? 1.f : 0.f;        // fire
                v[o] = vv * (1.f - s);                      // hard reset
                anys += s;
                outp[(size_t)o * HH * WW] = s;
            }
            if (anys != 0.f && t < firstloc) firstloc = t;
        }
        if (firstloc != INT_MAX) atomicMin(&g_first, firstloc);
    }
}

// Pass 2 (fallback): exact full simulation with grid barriers (validated R12
// kernel). Runs only if a spike was detected; zeroes its own state first.
__global__ __launch_bounds__(256, 4)
void k_fallback(const float* __restrict__ x_seq, float* __restrict__ out, int ngrid) {
    if (__ldcg(&g_first) == INT_MAX) return;     // fast path was exact

    __shared__ float trn[CIN][PH][PW2];
    __shared__ __align__(16) float tp_s[TH][TW][COUT];
    __shared__ unsigned long long xmask[CIN][PH];
    __shared__ unsigned int smask[TH][COUT];
    __shared__ __align__(16) float wt[50*COUT];
    __shared__ float red[NW][TH];
    __shared__ float sbuf[256];
    __shared__ int act_prior[2];

    const int tid = threadIdx.x;
    const int bid = blockIdx.x;
    unsigned bar_target = 0;

    // Zero state, then grid barrier.
    {
        const int gidx = bid*256 + tid, gstr = ngrid*256;
        for (int i = gidx; i < NB*COUT*HH*WW; i += gstr) { g_v[i] = 0.f; g_tp[i] = 0.f; }
        for (int i = gidx; i < NB*CIN*HP*WP; i += gstr) { g_trpre[0][i] = 0.f; g_trpre[1][i] = 0.f; }
    }
    bar_target += (unsigned)ngrid;
    __syncthreads();
    if (tid == 0) {
        __threadfence();
        atomicAdd(&g_bar_count, 1u);
        while (*(volatile unsigned*)&g_bar_count < bar_target) __nanosleep(128);
        __threadfence();
    }
    __syncthreads();

    for (int t = 0; t < T_STEPS; t++) {
        const int cur = t & 1;
        for (int j = tid; j < NW; j += 256) {
            int o = j / 50, tap = j - o * 50;
            wt[tap*COUT + o] = __ldcg(&g_w[j]);
        }

        for (int tile = bid; tile < NT; tile += ngrid) {
            const int b   = tile >> 6;
            const int ty0 = ((tile >> 2) & 15) * TH;
            const int tx0 = (tile & 3) * TW;

            __syncthreads();
            if (tid < CIN*PH) ((unsigned long long*)xmask)[tid] = 0ull;
            if (tid < 2) act_prior[tid] = __ldcg(&g_act[b*2 + tid]);
            __syncthreads();

            const float* xt  = x_seq + (((size_t)t*NB + b) * CIN) * HH * WW;
            const float* tro = g_trpre[cur]     + (size_t)b * CIN * HP * WP;
            float*       trw = g_trpre[cur ^ 1] + (size_t)b * CIN * HP * WP;

            const int ownH = (ty0 + TH == HH) ? PH : TH;
            const int ownW = (tx0 + TW == WW) ? PW : TW;

            for (int idx = tid; idx < CIN*PH*PW; idx += 256) {
                int i   = idx / (PH*PW);
                int rem = idx % (PH*PW);
                int r = rem / PW, c = rem % PW;
                int u = ty0 + r, vv = tx0 + c;
                int xr = u - PADL, xc = vv - PADL;
                float xv = 0.f;
                if (xr >= 0 && xr < HH && xc >= 0 && xc < WW)
                    xv = xt[(i*HH + xr)*WW + xc];
                float to = __ldcg(&tro[(i*HP + u)*WP + vv]);
                float tn = to - to / 30.0f + xv;
                trn[i][r][c] = tn;
                if (r < ownH && c < ownW)
                    trw[(i*HP + u)*WP + vv] = tn;
                if (xv != 0.f)
                    atomicOr(&xmask[i][r], 1ull << c);
            }
            __syncthreads();

            const int px = tid >> 5;
            const int py = tid & 31;
            int loc0, loc1;
            {
                float y[COUT];
                #pragma unroll
                for (int o = 0; o < COUT; o++) y[o] = 0.f;
                #pragma unroll
                for (int i = 0; i < CIN; i++) {
                    unsigned m = 0;
                    #pragma unroll
                    for (int kh = 0; kh < KK; kh++)
                        m |= (unsigned)((xmask[i][px + kh] >> py) & 0x1Full) << (kh*5);
                    while (m) {
                        int bpos = __ffs(m) - 1;
                        m &= m - 1;
                        const float* wp = &wt[(i*25 + bpos)*COUT];
                        float4 wa = *reinterpret_cast<const float4*>(wp);
                        float4 wb = *reinterpret_cast<const float4*>(wp + 4);
                        y[0] += wa.x; y[1] += wa.y; y[2] += wa.z; y[3] += wa.w;
                        y[4] += wb.x; y[5] += wb.y; y[6] += wb.z; y[7] += wb.w;
                    }
                }

                const int gx = ty0 + px, gy = tx0 + py;
                const size_t base = (size_t)b * COUT * HH * WW + (size_t)gx * WW + gy;
                float* outp = out + ((size_t)t * NB + b) * COUT * HH * WW + (size_t)gx * WW + gy;
                float tpv[COUT];
                unsigned ball[COUT];
                #pragma unroll
                for (int o = 0; o < COUT; o++) {
                    size_t gi = base + (size_t)o * HH * WW;
                    float v = g_v[gi];
                    v = v + (y[o] - v) / 100.0f;
                    float s = (v >= 1.0f) ? 1.f : 0.f;
                    v = v * (1.f - s);
                    g_v[gi] = v;
                    float tq = g_tp[gi];
                    tq = tq - tq / 30.0f + s;
                    g_tp[gi] = tq;
                    outp[(size_t)o * HH * WW] = s;
                    tpv[o] = tq;
                    ball[o] = __ballot_sync(0xffffffffu, s != 0.f);
                    if (py == 0) smask[px][o] = ball[o];
                }
                *reinterpret_cast<float4*>(&tp_s[px][py][0]) = make_float4(tpv[0], tpv[1], tpv[2], tpv[3]);
                *reinterpret_cast<float4*>(&tp_s[px][py][4]) = make_float4(tpv[4], tpv[5], tpv[6], tpv[7]);
                loc0 = (ball[0] | ball[1] | ball[2] | ball[3]) != 0;
                loc1 = (ball[4] | ball[5] | ball[6] | ball[7]) != 0;
            }
            const int any0 = __syncthreads_or(loc0);
            const int any1 = __syncthreads_or(loc1);
            if (tid == 0) {
                if (any0 && !act_prior[0]) atomicOr(&g_act[b*2 + 0], 1);
                if (any1 && !act_prior[1]) atomicOr(&g_act[b*2 + 1], 1);
                if (any0 | any1) atomicOr(&g_anyact, 1);
            }

            if (tid < 160) {
                const int qx = tid / 20;
                const int g  = tid - qx * 20;
                const int og = g & 1;
                const int ii = (g >> 1) & 1;
                const int kh = g >> 2;

                float a[KK][4];
                #pragma unroll
                for (int kw = 0; kw < KK; kw++)
                    #pragma unroll
                    for (int c = 0; c < 4; c++) a[kw][c] = 0.f;

                const int act = og ? (act_prior[1] | any1) : (act_prior[0] | any0);
                if (act) {
                    unsigned long long m = xmask[ii][qx + kh];
                    const float* tpr = &tp_s[qx][0][og*4];
                    while (m) {
                        int q = __ffsll(m) - 1;
                        m &= m - 1;
                        #pragma unroll
                        for (int kw = 0; kw < KK; kw++) {
                            int p2 = q - kw;
                            if ((unsigned)p2 < 32u) {
                                float4 tv = *reinterpret_cast<const float4*>(&tpr[p2*8]);
                                a[kw][0] += tv.x; a[kw][1] += tv.y;
                                a[kw][2] += tv.z; a[kw][3] += tv.w;
                            }
                        }
                    }
                }

                const float* urow = &trn[ii][qx + kh][0];
                #pragma unroll
                for (int c = 0; c < 4; c++) {
                    unsigned sm = smask[qx][og*4 + c];
                    while (sm) {
                        int p2 = __ffs(sm) - 1;
                        sm &= sm - 1;
                        #pragma unroll
                        for (int kw = 0; kw < KK; kw++)
                            a[kw][c] += urow[p2 + kw];
                    }
                }

                #pragma unroll
                for (int c = 0; c < 4; c++) {
                    const int o  = og*4 + c;
                    const int eb = ((o*CIN + ii)*KK + kh)*KK;
                    #pragma unroll
                    for (int kw = 0; kw < KK; kw++)
                        red[eb + kw][qx] = a[kw][c];
                }
            }
            __syncthreads();

            for (int e = tid; e < NW; e += 256) {
                float s = 0.f;
                #pragma unroll
                for (int j = 0; j < TH; j++) s += red[e][j];
                g_part[(size_t)e * NT + tile] = s;
            }
        }

        bar_target += (unsigned)ngrid;
        __syncthreads();
        if (tid == 0) {
            __threadfence();
            atomicAdd(&g_bar_count, 1u);
            while (*(volatile unsigned*)&g_bar_count < bar_target) __nanosleep(128);
            __threadfence();
        }
        __syncthreads();

        if (__ldcg(&g_anyact)) {
            if (bid < NW) {
                float s = 0.f;
                for (int j = tid; j < NT; j += 256)
                    s += __ldcg(&g_part[(size_t)bid * NT + j]);
                sbuf[tid] = s;
                __syncthreads();
                #pragma unroll
                for (int off = 128; off > 0; off >>= 1) {
                    if (tid < off) sbuf[tid] += sbuf[tid + off];
                    __syncthreads();
                }
                if (tid == 0)
                    g_w[bid] = __ldcg(&g_w[bid]) - 0.03f * sbuf[0];
            }
        }

        bar_target += (unsigned)ngrid;
        __syncthreads();
        if (tid == 0) {
            __threadfence();
            atomicAdd(&g_bar_count, 1u);
            while (*(volatile unsigned*)&g_bar_count < bar_target) __nanosleep(128);
            __threadfence();
        }
        __syncthreads();
    }
}

extern "C" void kernel_launch(void* const* d_in, const int* in_sizes, int n_in,
                              void* d_out, int out_size) {
    const float* x = (const float*)d_in[0];
    const float* w = (const float*)d_in[1];
    if (in_sizes[0] == NW) {
        x = (const float*)d_in[1];
        w = (const float*)d_in[0];
    }
    float* out = (float*)d_out;

    int perSM = 0, nsm = 0;
    cudaOccupancyMaxActiveBlocksPerMultiprocessor(&perSM, k_fallback, 256, 0);
    cudaDeviceGetAttribute(&nsm, cudaDevAttrMultiProcessorCount, 0);
    int ngrid = perSM * nsm;
    if (ngrid > NT) ngrid = NT;
    if (ngrid < 1)  ngrid = 1;

    k_init<<<1, 512>>>(w);
    k_masks<<<2048, 256>>>(x);
    k_fast<<<NT, 256>>>(out);
    k_fallback<<<ngrid, 256>>>(x, out, ngrid);
}

// round 14
// speedup vs baseline: 5.1130x; 1.0035x over previous
#include <cuda_runtime.h>
#include <climits>

// Problem dims
#define T_STEPS 32
#define NB      16
#define CIN     2
#define COUT    8
#define HH      128
#define WW      128
#define KK      5
#define PADL    2
#define HP      (HH + 2*PADL)   // 132
#define WP      (WW + 2*PADL)   // 132
#define NW      (COUT*CIN*KK*KK) // 400

// Tiling
#define TH 8
#define TW 32
#define PH (TH + 4)   // 12
#define PW 36
#define PW2 37
#define NT ((WW/TW) * (HH/TH) * NB)   // 1024 tiles
#define NROWS (T_STEPS*NB*CIN*HH)     // 131072 mask rows

// Persistent state (device globals: allocation-free)
__device__ float g_v[NB*COUT*HH*WW];
__device__ float g_tp[NB*COUT*HH*WW];
__device__ float g_trpre[2][NB*CIN*HP*WP];
__device__ float g_w[NW];
__device__ float g_part[NW * NT];
__device__ int   g_act[NB*2];
__device__ int   g_anyact;
__device__ unsigned g_bar_count;
__device__ ulonglong2 g_xm[NROWS];    // 128-bit x row masks, 2MB
__device__ int   g_first;             // first spike step anywhere, or INT_MAX

__global__ void k_init(const float* __restrict__ w0) {
    int idx = threadIdx.x;
    if (idx < NW) g_w[idx] = w0[idx];
    if (idx < NB*2) g_act[idx] = 0;
    if (idx == 0) { g_anyact = 0; g_bar_count = 0u; g_first = INT_MAX; }
}

// Pass 0: build binary x masks for all (t, b, i, row).
__global__ void k_masks(const float* __restrict__ x) {
    const int nwarps = (gridDim.x * blockDim.x) >> 5;
    const int wid = (blockIdx.x * blockDim.x + threadIdx.x) >> 5;
    const int l = threadIdx.x & 31;
    for (int row = wid; row < NROWS; row += nwarps) {
        const float* xr = x + (size_t)row * WW;
        unsigned b0 = __ballot_sync(0xffffffffu, xr[l       ] != 0.f);
        unsigned b1 = __ballot_sync(0xffffffffu, xr[l + 32  ] != 0.f);
        unsigned b2 = __ballot_sync(0xffffffffu, xr[l + 64  ] != 0.f);
        unsigned b3 = __ballot_sync(0xffffffffu, xr[l + 96  ] != 0.f);
        if (l == 0)
            g_xm[row] = make_ulonglong2(b0 | ((unsigned long long)b1 << 32),
                                        b2 | ((unsigned long long)b3 << 32));
    }
}

// Pass 1 (speculative fast path): per-tile fully-local simulation, weights
// fixed at w0. Exact while no spike occurs anywhere (then dw == 0 exactly and
// traces are unobservable). Records the earliest spike step in g_first.
__global__ __launch_bounds__(256)
void k_fast(float* __restrict__ out) {
    __shared__ __align__(16) float wt[50*COUT];   // weights transposed [tap][o]
    __shared__ unsigned long long xm[CIN][PH];

    const int tid = threadIdx.x;
    for (int j = tid; j < NW; j += 256) {
        int o = j / 50, tap = j - o * 50;
        wt[tap*COUT + o] = g_w[j];                 // == w0 for this whole pass
    }
    const int px = tid >> 5;
    const int py = tid & 31;

    for (int tile = blockIdx.x; tile < NT; tile += gridDim.x) {
        const int b   = tile >> 6;
        const int ty0 = ((tile >> 2) & 15) * TH;
        const int tx0 = (tile & 3) * TW;
        const int gx = ty0 + px, gy = tx0 + py;

        float v[COUT];
        #pragma unroll
        for (int o = 0; o < COUT; o++) v[o] = 0.f;

        int firstloc = INT_MAX;
        for (int t = 0; t < T_STEPS; t++) {
            __syncthreads();
            if (tid < CIN*PH) {
                const int i = tid / PH, r = tid - i*PH;
                const int xr = ty0 - PADL + r;
                unsigned long long win = 0ull;
                if ((unsigned)xr < (unsigned)HH) {
                    ulonglong2 m = g_xm[((t*NB + b)*CIN + i)*HH + xr];
                    if (tx0 == 0) win = m.x << 2;
                    else {
                        int s = tx0 - PADL;        // 30, 62, 94
                        win = (s < 64) ? ((m.x >> s) | (m.y << (64 - s)))
                                       : (m.y >> (s - 64));
                    }
                    win &= (1ull << 36) - 1;
                }
                xm[i][r] = win;
            }
            __syncthreads();

            float y[COUT];
            #pragma unroll
            for (int o = 0; o < COUT; o++) y[o] = 0.f;
            #pragma unroll
            for (int i = 0; i < CIN; i++) {
                unsigned m = 0;
                #pragma unroll
                for (int kh = 0; kh < KK; kh++)
                    m |= (unsigned)((xm[i][px + kh] >> py) & 0x1Full) << (kh*5);
                while (m) {
                    int bp = __ffs(m) - 1;
                    m &= m - 1;
                    const float* wp = &wt[(i*25 + bp)*COUT];
                    float4 wa = *reinterpret_cast<const float4*>(wp);
                    float4 wb = *reinterpret_cast<const float4*>(wp + 4);
                    y[0] += wa.x; y[1] += wa.y; y[2] += wa.z; y[3] += wa.w;
                    y[4] += wb.x; y[5] += wb.y; y[6] += wb.z; y[7] += wb.w;
                }
            }

            float* outp = out + ((size_t)t*NB + b)*COUT*HH*WW + (size_t)gx*WW + gy;
            float anys = 0.f;
            #pragma unroll
            for (int o = 0; o < COUT; o++) {
                float vv = v[o] + (y[o] - v[o]) / 100.0f;   // LIF charge
                float s  = (vv >= 1.0f) ? 1.f : 0.f;        // fire
                v[o] = vv * (1.f - s);                      // hard reset
                anys += s;
                outp[(size_t)o * HH * WW] = s;
            }
            if (anys != 0.f && t < firstloc) firstloc = t;
        }
        if (firstloc != INT_MAX) atomicMin(&g_first, firstloc);
    }
}

// Pass 2 (fallback): exact full simulation with grid barriers (validated R12
// kernel). Runs only if a spike was detected; zeroes its own state first.
__global__ __launch_bounds__(256, 4)
void k_fallback(const float* __restrict__ x_seq, float* __restrict__ out, int ngrid) {
    if (__ldcg(&g_first) == INT_MAX) return;     // fast path was exact

    __shared__ float trn[CIN][PH][PW2];
    __shared__ __align__(16) float tp_s[TH][TW][COUT];
    __shared__ unsigned long long xmask[CIN][PH];
    __shared__ unsigned int smask[TH][COUT];
    __shared__ __align__(16) float wt[50*COUT];
    __shared__ float red[NW][TH];
    __shared__ float sbuf[256];
    __shared__ int act_prior[2];

    const int tid = threadIdx.x;
    const int bid = blockIdx.x;
    unsigned bar_target = 0;

    // Zero state, then grid barrier.
    {
        const int gidx = bid*256 + tid, gstr = ngrid*256;
        for (int i = gidx; i < NB*COUT*HH*WW; i += gstr) { g_v[i] = 0.f; g_tp[i] = 0.f; }
        for (int i = gidx; i < NB*CIN*HP*WP; i += gstr) { g_trpre[0][i] = 0.f; g_trpre[1][i] = 0.f; }
    }
    bar_target += (unsigned)ngrid;
    __syncthreads();
    if (tid == 0) {
        __threadfence();
        atomicAdd(&g_bar_count, 1u);
        while (*(volatile unsigned*)&g_bar_count < bar_target) __nanosleep(128);
        __threadfence();
    }
    __syncthreads();

    for (int t = 0; t < T_STEPS; t++) {
        const int cur = t & 1;
        for (int j = tid; j < NW; j += 256) {
            int o = j / 50, tap = j - o * 50;
            wt[tap*COUT + o] = __ldcg(&g_w[j]);
        }

        for (int tile = bid; tile < NT; tile += ngrid) {
            const int b   = tile >> 6;
            const int ty0 = ((tile >> 2) & 15) * TH;
            const int tx0 = (tile & 3) * TW;

            __syncthreads();
            if (tid < CIN*PH) ((unsigned long long*)xmask)[tid] = 0ull;
            if (tid < 2) act_prior[tid] = __ldcg(&g_act[b*2 + tid]);
            __syncthreads();

            const float* xt  = x_seq + (((size_t)t*NB + b) * CIN) * HH * WW;
            const float* tro = g_trpre[cur]     + (size_t)b * CIN * HP * WP;
            float*       trw = g_trpre[cur ^ 1] + (size_t)b * CIN * HP * WP;

            const int ownH = (ty0 + TH == HH) ? PH : TH;
            const int ownW = (tx0 + TW == WW) ? PW : TW;

            for (int idx = tid; idx < CIN*PH*PW; idx += 256) {
                int i   = idx / (PH*PW);
                int rem = idx % (PH*PW);
                int r = rem / PW, c = rem % PW;
                int u = ty0 + r, vv = tx0 + c;
                int xr = u - PADL, xc = vv - PADL;
                float xv = 0.f;
                if (xr >= 0 && xr < HH && xc >= 0 && xc < WW)
                    xv = xt[(i*HH + xr)*WW + xc];
                float to = __ldcg(&tro[(i*HP + u)*WP + vv]);
                float tn = to - to / 30.0f + xv;
                trn[i][r][c] = tn;
                if (r < ownH && c < ownW)
                    trw[(i*HP + u)*WP + vv] = tn;
                if (xv != 0.f)
                    atomicOr(&xmask[i][r], 1ull << c);
            }
            __syncthreads();

            const int px = tid >> 5;
            const int py = tid & 31;
            int loc0, loc1;
            {
                float y[COUT];
                #pragma unroll
                for (int o = 0; o < COUT; o++) y[o] = 0.f;
                #pragma unroll
                for (int i = 0; i < CIN; i++) {
                    unsigned m = 0;
                    #pragma unroll
                    for (int kh = 0; kh < KK; kh++)
                        m |= (unsigned)((xmask[i][px + kh] >> py) & 0x1Full) << (kh*5);
                    while (m) {
                        int bpos = __ffs(m) - 1;
                        m &= m - 1;
                        const float* wp = &wt[(i*25 + bpos)*COUT];
                        float4 wa = *reinterpret_cast<const float4*>(wp);
                        float4 wb = *reinterpret_cast<const float4*>(wp + 4);
                        y[0] += wa.x; y[1] += wa.y; y[2] += wa.z; y[3] += wa.w;
                        y[4] += wb.x; y[5] += wb.y; y[6] += wb.z; y[7] += wb.w;
                    }
                }

                const int gx = ty0 + px, gy = tx0 + py;
                const size_t base = (size_t)b * COUT * HH * WW + (size_t)gx * WW + gy;
                float* outp = out + ((size_t)t * NB + b) * COUT * HH * WW + (size_t)gx * WW + gy;
                float tpv[COUT];
                unsigned ball[COUT];
                #pragma unroll
                for (int o = 0; o < COUT; o++) {
                    size_t gi = base + (size_t)o * HH * WW;
                    float v = g_v[gi];
                    v = v + (y[o] - v) / 100.0f;
                    float s = (v >= 1.0f) ? 1.f : 0.f;
                    v = v * (1.f - s);
                    g_v[gi] = v;
                    float tq = g_tp[gi];
                    tq = tq - tq / 30.0f + s;
                    g_tp[gi] = tq;
                    outp[(size_t)o * HH * WW] = s;
                    tpv[o] = tq;
                    ball[o] = __ballot_sync(0xffffffffu, s != 0.f);
                    if (py == 0) smask[px][o] = ball[o];
                }
                *reinterpret_cast<float4*>(&tp_s[px][py][0]) = make_float4(tpv[0], tpv[1], tpv[2], tpv[3]);
                *reinterpret_cast<float4*>(&tp_s[px][py][4]) = make_float4(tpv[4], tpv[5], tpv[6], tpv[7]);
                loc0 = (ball[0] | ball[1] | ball[2] | ball[3]) != 0;
                loc1 = (ball[4] | ball[5] | ball[6] | ball[7]) != 0;
            }
            const int any0 = __syncthreads_or(loc0);
            const int any1 = __syncthreads_or(loc1);
            if (tid == 0) {
                if (any0 && !act_prior[0]) atomicOr(&g_act[b*2 + 0], 1);
                if (any1 && !act_prior[1]) atomicOr(&g_act[b*2 + 1], 1);
                if (any0 | any1) atomicOr(&g_anyact, 1);
            }

            if (tid < 160) {
                const int qx = tid / 20;
                const int g  = tid - qx * 20;
                const int og = g & 1;
                const int ii = (g >> 1) & 1;
                const int kh = g >> 2;

                float a[KK][4];
                #pragma unroll
                for (int kw = 0; kw < KK; kw++)
                    #pragma unroll
                    for (int c = 0; c < 4; c++) a[kw][c] = 0.f;

                const int act = og ? (act_prior[1] | any1) : (act_prior[0] | any0);
                if (act) {
                    unsigned long long m = xmask[ii][qx + kh];
                    const float* tpr = &tp_s[qx][0][og*4];
                    while (m) {
                        int q = __ffsll(m) - 1;
                        m &= m - 1;
                        #pragma unroll
                        for (int kw = 0; kw < KK; kw++) {
                            int p2 = q - kw;
                            if ((unsigned)p2 < 32u) {
                                float4 tv = *reinterpret_cast<const float4*>(&tpr[p2*8]);
                                a[kw][0] += tv.x; a[kw][1] += tv.y;
                                a[kw][2] += tv.z; a[kw][3] += tv.w;
                            }
                        }
                    }
                }

                const float* urow = &trn[ii][qx + kh][0];
                #pragma unroll
                for (int c = 0; c < 4; c++) {
                    unsigned sm = smask[qx][og*4 + c];
                    while (sm) {
                        int p2 = __ffs(sm) - 1;
                        sm &= sm - 1;
                        #pragma unroll
                        for (int kw = 0; kw < KK; kw++)
                            a[kw][c] += urow[p2 + kw];
                    }
                }

                #pragma unroll
                for (int c = 0; c < 4; c++) {
                    const int o  = og*4 + c;
                    const int eb = ((o*CIN + ii)*KK + kh)*KK;
                    #pragma unroll
                    for (int kw = 0; kw < KK; kw++)
                        red[eb + kw][qx] = a[kw][c];
                }
            }
            __syncthreads();

            for (int e = tid; e < NW; e += 256) {
                float s = 0.f;
                #pragma unroll
                for (int j = 0; j < TH; j++) s += red[e][j];
                g_part[(size_t)e * NT + tile] = s;
            }
        }

        bar_target += (unsigned)ngrid;
        __syncthreads();
        if (tid == 0) {
            __threadfence();
            atomicAdd(&g_bar_count, 1u);
            while (*(volatile unsigned*)&g_bar_count < bar_target) __nanosleep(128);
            __threadfence();
        }
        __syncthreads();

        if (__ldcg(&g_anyact)) {
            if (bid < NW) {
                float s = 0.f;
                for (int j = tid; j < NT; j += 256)
                    s += __ldcg(&g_part[(size_t)bid * NT + j]);
                sbuf[tid] = s;
                __syncthreads();
                #pragma unroll
                for (int off = 128; off > 0; off >>= 1) {
                    if (tid < off) sbuf[tid] += sbuf[tid + off];
                    __syncthreads();
                }
                if (tid == 0)
                    g_w[bid] = __ldcg(&g_w[bid]) - 0.03f * sbuf[0];
            }
        }

        bar_target += (unsigned)ngrid;
        __syncthreads();
        if (tid == 0) {
            __threadfence();
            atomicAdd(&g_bar_count, 1u);
            while (*(volatile unsigned*)&g_bar_count < bar_target) __nanosleep(128);
            __threadfence();
        }
        __syncthreads();
    }
}

extern "C" void kernel_launch(void* const* d_in, const int* in_sizes, int n_in,
                              void* d_out, int out_size) {
    const float* x = (const float*)d_in[0];
    const float* w = (const float*)d_in[1];
    if (in_sizes[0] == NW) {
        x = (const float*)d_in[1];
        w = (const float*)d_in[0];
    }
    float* out = (float*)d_out;

    int perSM = 0, nsm = 0;
    cudaOccupancyMaxActiveBlocksPerMultiprocessor(&perSM, k_fallback, 256, 0);
    cudaDeviceGetAttribute(&nsm, cudaDevAttrMultiProcessorCount, 0);
    int ngrid = perSM * nsm;
    if (ngrid > NT) ngrid = NT;
    if (ngrid < 1)  ngrid = 1;

    k_init<<<1, 512>>>(w);
    k_masks<<<2048, 256>>>(x);
    k_fast<<<NT, 256>>>(out);
    k_fallback<<<ngrid, 256>>>(x, out, ngrid);
}

// round 15
// speedup vs baseline: 5.1267x; 1.0027x over previous
#include <cuda_runtime.h>
#include <climits>

// Problem dims
#define T_STEPS 32
#define NB      16
#define CIN     2
#define COUT    8
#define HH      128
#define WW      128
#define KK      5
#define PADL    2
#define HP      (HH + 2*PADL)   // 132
#define WP      (WW + 2*PADL)   // 132
#define NW      (COUT*CIN*KK*KK) // 400

// Tiling
#define TH 8
#define TW 32
#define PH (TH + 4)   // 12
#define PW 36
#define PW2 37
#define NT ((WW/TW) * (HH/TH) * NB)   // 1024 tiles
#define NROWS (T_STEPS*NB*CIN*HH)     // 131072 mask rows

// Persistent state (device globals: allocation-free)
__device__ float g_v[NB*COUT*HH*WW];
__device__ float g_tp[NB*COUT*HH*WW];
__device__ float g_trpre[2][NB*CIN*HP*WP];
__device__ float g_w[NW];
__device__ float g_part[NW * NT];
__device__ int   g_act[NB*2];
__device__ int   g_anyact;
__device__ unsigned g_bar_count;
__device__ ulonglong2 g_xm[NROWS];    // 128-bit x row masks, 2MB
__device__ int   g_first;             // first spike step anywhere, or INT_MAX

__global__ void k_init(const float* __restrict__ w0) {
    int idx = threadIdx.x;
    if (idx < NW) g_w[idx] = w0[idx];
    if (idx < NB*2) g_act[idx] = 0;
    if (idx == 0) { g_anyact = 0; g_bar_count = 0u; g_first = INT_MAX; }
}

// Pass 0: build binary x masks for all (t, b, i, row).
__global__ void k_masks(const float* __restrict__ x) {
    const int nwarps = (gridDim.x * blockDim.x) >> 5;
    const int wid = (blockIdx.x * blockDim.x + threadIdx.x) >> 5;
    const int l = threadIdx.x & 31;
    for (int row = wid; row < NROWS; row += nwarps) {
        const float* xr = x + (size_t)row * WW;
        unsigned b0 = __ballot_sync(0xffffffffu, xr[l       ] != 0.f);
        unsigned b1 = __ballot_sync(0xffffffffu, xr[l + 32  ] != 0.f);
        unsigned b2 = __ballot_sync(0xffffffffu, xr[l + 64  ] != 0.f);
        unsigned b3 = __ballot_sync(0xffffffffu, xr[l + 96  ] != 0.f);
        if (l == 0)
            g_xm[row] = make_ulonglong2(b0 | ((unsigned long long)b1 << 32),
                                        b2 | ((unsigned long long)b3 << 32));
    }
}

// Pass 1 (speculative fast path): per-tile fully-local simulation, weights
// fixed at w0. Exact while no spike occurs anywhere (then dw == 0 exactly and
// traces are unobservable). Records the earliest spike step in g_first.
__global__ __launch_bounds__(256)
void k_fast(float* __restrict__ out) {
    __shared__ __align__(16) float wt[50*COUT];   // weights transposed [tap][o]
    __shared__ unsigned long long xm[CIN][PH];

    const int tid = threadIdx.x;
    for (int j = tid; j < NW; j += 256) {
        int o = j / 50, tap = j - o * 50;
        wt[tap*COUT + o] = g_w[j];                 // == w0 for this whole pass
    }
    const int px = tid >> 5;
    const int py = tid & 31;

    for (int tile = blockIdx.x; tile < NT; tile += gridDim.x) {
        const int b   = tile >> 6;
        const int ty0 = ((tile >> 2) & 15) * TH;
        const int tx0 = (tile & 3) * TW;
        const int gx = ty0 + px, gy = tx0 + py;

        float v[COUT];
        #pragma unroll
        for (int o = 0; o < COUT; o++) v[o] = 0.f;

        int firstloc = INT_MAX;
        for (int t = 0; t < T_STEPS; t++) {
            __syncthreads();
            if (tid < CIN*PH) {
                const int i = tid / PH, r = tid - i*PH;
                const int xr = ty0 - PADL + r;
                unsigned long long win = 0ull;
                if ((unsigned)xr < (unsigned)HH) {
                    ulonglong2 m = g_xm[((t*NB + b)*CIN + i)*HH + xr];
                    if (tx0 == 0) win = m.x << 2;
                    else {
                        int s = tx0 - PADL;        // 30, 62, 94
                        win = (s < 64) ? ((m.x >> s) | (m.y << (64 - s)))
                                       : (m.y >> (s - 64));
                    }
                    win &= (1ull << 36) - 1;
                }
                xm[i][r] = win;
            }
            __syncthreads();

            float y[COUT];
            #pragma unroll
            for (int o = 0; o < COUT; o++) y[o] = 0.f;
            #pragma unroll
            for (int i = 0; i < CIN; i++) {
                unsigned m = 0;
                #pragma unroll
                for (int kh = 0; kh < KK; kh++)
                    m |= (unsigned)((xm[i][px + kh] >> py) & 0x1Full) << (kh*5);
                while (m) {
                    int bp = __ffs(m) - 1;
                    m &= m - 1;
                    const float* wp = &wt[(i*25 + bp)*COUT];
                    float4 wa = *reinterpret_cast<const float4*>(wp);
                    float4 wb = *reinterpret_cast<const float4*>(wp + 4);
                    y[0] += wa.x; y[1] += wa.y; y[2] += wa.z; y[3] += wa.w;
                    y[4] += wb.x; y[5] += wb.y; y[6] += wb.z; y[7] += wb.w;
                }
            }

            float* outp = out + ((size_t)t*NB + b)*COUT*HH*WW + (size_t)gx*WW + gy;
            float anys = 0.f;
            #pragma unroll
            for (int o = 0; o < COUT; o++) {
                float vv = v[o] + (y[o] - v[o]) / 100.0f;   // LIF charge
                float s  = (vv >= 1.0f) ? 1.f : 0.f;        // fire
                v[o] = vv * (1.f - s);                      // hard reset
                anys += s;
                outp[(size_t)o * HH * WW] = s;
            }
            if (anys != 0.f && t < firstloc) firstloc = t;
        }
        if (firstloc != INT_MAX) atomicMin(&g_first, firstloc);
    }
}

// Pass 2 (fallback): exact full simulation with grid barriers (validated R12
// kernel). Runs only if a spike was detected; zeroes its own state first.
__global__ __launch_bounds__(256, 4)
void k_fallback(const float* __restrict__ x_seq, float* __restrict__ out, int ngrid) {
    if (__ldcg(&g_first) == INT_MAX) return;     // fast path was exact

    __shared__ float trn[CIN][PH][PW2];
    __shared__ __align__(16) float tp_s[TH][TW][COUT];
    __shared__ unsigned long long xmask[CIN][PH];
    __shared__ unsigned int smask[TH][COUT];
    __shared__ __align__(16) float wt[50*COUT];
    __shared__ float red[NW][TH];
    __shared__ float sbuf[256];
    __shared__ int act_prior[2];

    const int tid = threadIdx.x;
    const int bid = blockIdx.x;
    unsigned bar_target = 0;

    // Zero state, then grid barrier.
    {
        const int gidx = bid*256 + tid, gstr = ngrid*256;
        for (int i = gidx; i < NB*COUT*HH*WW; i += gstr) { g_v[i] = 0.f; g_tp[i] = 0.f; }
        for (int i = gidx; i < NB*CIN*HP*WP; i += gstr) { g_trpre[0][i] = 0.f; g_trpre[1][i] = 0.f; }
    }
    bar_target += (unsigned)ngrid;
    __syncthreads();
    if (tid == 0) {
        __threadfence();
        atomicAdd(&g_bar_count, 1u);
        while (*(volatile unsigned*)&g_bar_count < bar_target) __nanosleep(128);
        __threadfence();
    }
    __syncthreads();

    for (int t = 0; t < T_STEPS; t++) {
        const int cur = t & 1;
        for (int j = tid; j < NW; j += 256) {
            int o = j / 50, tap = j - o * 50;
            wt[tap*COUT + o] = __ldcg(&g_w[j]);
        }

        for (int tile = bid; tile < NT; tile += ngrid) {
            const int b   = tile >> 6;
            const int ty0 = ((tile >> 2) & 15) * TH;
            const int tx0 = (tile & 3) * TW;

            __syncthreads();
            if (tid < CIN*PH) ((unsigned long long*)xmask)[tid] = 0ull;
            if (tid < 2) act_prior[tid] = __ldcg(&g_act[b*2 + tid]);
            __syncthreads();

            const float* xt  = x_seq + (((size_t)t*NB + b) * CIN) * HH * WW;
            const float* tro = g_trpre[cur]     + (size_t)b * CIN * HP * WP;
            float*       trw = g_trpre[cur ^ 1] + (size_t)b * CIN * HP * WP;

            const int ownH = (ty0 + TH == HH) ? PH : TH;
            const int ownW = (tx0 + TW == WW) ? PW : TW;

            for (int idx = tid; idx < CIN*PH*PW; idx += 256) {
                int i   = idx / (PH*PW);
                int rem = idx % (PH*PW);
                int r = rem / PW, c = rem % PW;
                int u = ty0 + r, vv = tx0 + c;
                int xr = u - PADL, xc = vv - PADL;
                float xv = 0.f;
                if (xr >= 0 && xr < HH && xc >= 0 && xc < WW)
                    xv = xt[(i*HH + xr)*WW + xc];
                float to = __ldcg(&tro[(i*HP + u)*WP + vv]);
                float tn = to - to / 30.0f + xv;
                trn[i][r][c] = tn;
                if (r < ownH && c < ownW)
                    trw[(i*HP + u)*WP + vv] = tn;
                if (xv != 0.f)
                    atomicOr(&xmask[i][r], 1ull << c);
            }
            __syncthreads();

            const int px = tid >> 5;
            const int py = tid & 31;
            int loc0, loc1;
            {
                float y[COUT];
                #pragma unroll
                for (int o = 0; o < COUT; o++) y[o] = 0.f;
                #pragma unroll
                for (int i = 0; i < CIN; i++) {
                    unsigned m = 0;
                    #pragma unroll
                    for (int kh = 0; kh < KK; kh++)
                        m |= (unsigned)((xmask[i][px + kh] >> py) & 0x1Full) << (kh*5);
                    while (m) {
                        int bpos = __ffs(m) - 1;
                        m &= m - 1;
                        const float* wp = &wt[(i*25 + bpos)*COUT];
                        float4 wa = *reinterpret_cast<const float4*>(wp);
                        float4 wb = *reinterpret_cast<const float4*>(wp + 4);
                        y[0] += wa.x; y[1] += wa.y; y[2] += wa.z; y[3] += wa.w;
                        y[4] += wb.x; y[5] += wb.y; y[6] += wb.z; y[7] += wb.w;
                    }
                }

                const int gx = ty0 + px, gy = tx0 + py;
                const size_t base = (size_t)b * COUT * HH * WW + (size_t)gx * WW + gy;
                float* outp = out + ((size_t)t * NB + b) * COUT * HH * WW + (size_t)gx * WW + gy;
                float tpv[COUT];
                unsigned ball[COUT];
                #pragma unroll
                for (int o = 0; o < COUT; o++) {
                    size_t gi = base + (size_t)o * HH * WW;
                    float v = g_v[gi];
                    v = v + (y[o] - v) / 100.0f;
                    float s = (v >= 1.0f) ? 1.f : 0.f;
                    v = v * (1.f - s);
                    g_v[gi] = v;
                    float tq = g_tp[gi];
                    tq = tq - tq / 30.0f + s;
                    g_tp[gi] = tq;
                    outp[(size_t)o * HH * WW] = s;
                    tpv[o] = tq;
                    ball[o] = __ballot_sync(0xffffffffu, s != 0.f);
                    if (py == 0) smask[px][o] = ball[o];
                }
                *reinterpret_cast<float4*>(&tp_s[px][py][0]) = make_float4(tpv[0], tpv[1], tpv[2], tpv[3]);
                *reinterpret_cast<float4*>(&tp_s[px][py][4]) = make_float4(tpv[4], tpv[5], tpv[6], tpv[7]);
                loc0 = (ball[0] | ball[1] | ball[2] | ball[3]) != 0;
                loc1 = (ball[4] | ball[5] | ball[6] | ball[7]) != 0;
            }
            const int any0 = __syncthreads_or(loc0);
            const int any1 = __syncthreads_or(loc1);
            if (tid == 0) {
                if (any0 && !act_prior[0]) atomicOr(&g_act[b*2 + 0], 1);
                if (any1 && !act_prior[1]) atomicOr(&g_act[b*2 + 1], 1);
                if (any0 | any1) atomicOr(&g_anyact, 1);
            }

            if (tid < 160) {
                const int qx = tid / 20;
                const int g  = tid - qx * 20;
                const int og = g & 1;
                const int ii = (g >> 1) & 1;
                const int kh = g >> 2;

                float a[KK][4];
                #pragma unroll
                for (int kw = 0; kw < KK; kw++)
                    #pragma unroll
                    for (int c = 0; c < 4; c++) a[kw][c] = 0.f;

                const int act = og ? (act_prior[1] | any1) : (act_prior[0] | any0);
                if (act) {
                    unsigned long long m = xmask[ii][qx + kh];
                    const float* tpr = &tp_s[qx][0][og*4];
                    while (m) {
                        int q = __ffsll(m) - 1;
                        m &= m - 1;
                        #pragma unroll
                        for (int kw = 0; kw < KK; kw++) {
                            int p2 = q - kw;
                            if ((unsigned)p2 < 32u) {
                                float4 tv = *reinterpret_cast<const float4*>(&tpr[p2*8]);
                                a[kw][0] += tv.x; a[kw][1] += tv.y;
                                a[kw][2] += tv.z; a[kw][3] += tv.w;
                            }
                        }
                    }
                }

                const float* urow = &trn[ii][qx + kh][0];
                #pragma unroll
                for (int c = 0; c < 4; c++) {
                    unsigned sm = smask[qx][og*4 + c];
                    while (sm) {
                        int p2 = __ffs(sm) - 1;
                        sm &= sm - 1;
                        #pragma unroll
                        for (int kw = 0; kw < KK; kw++)
                            a[kw][c] += urow[p2 + kw];
                    }
                }

                #pragma unroll
                for (int c = 0; c < 4; c++) {
                    const int o  = og*4 + c;
                    const int eb = ((o*CIN + ii)*KK + kh)*KK;
                    #pragma unroll
                    for (int kw = 0; kw < KK; kw++)
                        red[eb + kw][qx] = a[kw][c];
                }
            }
            __syncthreads();

            for (int e = tid; e < NW; e += 256) {
                float s = 0.f;
                #pragma unroll
                for (int j = 0; j < TH; j++) s += red[e][j];
                g_part[(size_t)e * NT + tile] = s;
            }
        }

        bar_target += (unsigned)ngrid;
        __syncthreads();
        if (tid == 0) {
            __threadfence();
            atomicAdd(&g_bar_count, 1u);
            while (*(volatile unsigned*)&g_bar_count < bar_target) __nanosleep(128);
            __threadfence();
        }
        __syncthreads();

        if (__ldcg(&g_anyact)) {
            if (bid < NW) {
                float s = 0.f;
                for (int j = tid; j < NT; j += 256)
                    s += __ldcg(&g_part[(size_t)bid * NT + j]);
                sbuf[tid] = s;
                __syncthreads();
                #pragma unroll
                for (int off = 128; off > 0; off >>= 1) {
                    if (tid < off) sbuf[tid] += sbuf[tid + off];
                    __syncthreads();
                }
                if (tid == 0)
                    g_w[bid] = __ldcg(&g_w[bid]) - 0.03f * sbuf[0];
            }
        }

        bar_target += (unsigned)ngrid;
        __syncthreads();
        if (tid == 0) {
            __threadfence();
            atomicAdd(&g_bar_count, 1u);
            while (*(volatile unsigned*)&g_bar_count < bar_target) __nanosleep(128);
            __threadfence();
        }
        __syncthreads();
    }
}

extern "C" void kernel_launch(void* const* d_in, const int* in_sizes, int n_in,
                              void* d_out, int out_size) {
    const float* x = (const float*)d_in[0];
    const float* w = (const float*)d_in[1];
    if (in_sizes[0] == NW) {
        x = (const float*)d_in[1];
        w = (const float*)d_in[0];
    }
    float* out = (float*)d_out;

    int perSM = 0, nsm = 0;
    cudaOccupancyMaxActiveBlocksPerMultiprocessor(&perSM, k_fallback, 256, 0);
    cudaDeviceGetAttribute(&nsm, cudaDevAttrMultiProcessorCount, 0);
    int ngrid = perSM * nsm;
    if (ngrid > NT) ngrid = NT;
    if (ngrid < 1)  ngrid = 1;

    k_init<<<1, 512>>>(w);
    k_masks<<<2048, 256>>>(x);
    k_fast<<<NT, 256>>>(out);
    k_fallback<<<ngrid, 256>>>(x, out, ngrid);
}